// round 1
// baseline (speedup 1.0000x reference)
#include <cuda_runtime.h>
#include <cstdint>

// Problem constants
#define BATCH 32
#define CC 2048       // channels
#define PP 196        // H*W
#define GG 20         // decoder steps
#define DD 1024       // decode size
#define AA 512        // att size

// Scratch (static device globals: allowed; no runtime allocation)
__device__ float g_att_enc[BATCH * PP * AA];   // (B, P, A) 12.8 MB
__device__ float g_att_dec[BATCH * GG * AA];   // (B, G, A) 1.3 MB

// ---------------------------------------------------------------------------
// K1: att_enc[b*P+p][a] = sum_k enc[b, k, p] * W_enc[k, a] + b_enc[a]
//     M = 6272 (b,p), N = 512, K = 2048. A-operand is transposed in memory
//     (k-major with stride P), so we load it m-fastest (contiguous along p).
// 128x128x8 tile, 256 threads, 8x8 per thread.
// ---------------------------------------------------------------------------
__global__ __launch_bounds__(256) void k_att_enc(
    const float* __restrict__ enc, const float* __restrict__ W,
    const float* __restrict__ bias, float* __restrict__ out)
{
    __shared__ float As[8][128];
    __shared__ float Bs[8][128];

    const int m0 = blockIdx.y * 128;
    const int n0 = blockIdx.x * 128;
    const int t  = threadIdx.x;
    const int tr = t >> 4;   // 0..15
    const int tc = t & 15;   // 0..15

    // Precompute per-thread load indices (fixed across k-tiles)
    int kIdx[4], mIdx[4];
    size_t baseA[4];
    #pragma unroll
    for (int i = 0; i < 4; i++) {
        int e = t + i * 256;          // 0..1023
        kIdx[i] = e >> 7;             // 0..7
        mIdx[i] = e & 127;            // 0..127
        int gm = m0 + mIdx[i];        // < 6272 (exact tiling)
        int b  = gm / PP;
        int p  = gm - b * PP;
        baseA[i] = (size_t)b * CC * PP + p;
    }

    float acc[8][8];
    #pragma unroll
    for (int i = 0; i < 8; i++)
        #pragma unroll
        for (int j = 0; j < 8; j++) acc[i][j] = 0.f;

    for (int k0 = 0; k0 < CC; k0 += 8) {
        #pragma unroll
        for (int i = 0; i < 4; i++) {
            As[kIdx[i]][mIdx[i]] = enc[baseA[i] + (size_t)(k0 + kIdx[i]) * PP];
            Bs[kIdx[i]][mIdx[i]] = W[(size_t)(k0 + kIdx[i]) * AA + n0 + mIdx[i]];
        }
        __syncthreads();

        #pragma unroll
        for (int kk = 0; kk < 8; kk++) {
            float4 a0 = *(const float4*)&As[kk][tr * 8];
            float4 a1 = *(const float4*)&As[kk][tr * 8 + 4];
            float4 b0 = *(const float4*)&Bs[kk][tc * 8];
            float4 b1 = *(const float4*)&Bs[kk][tc * 8 + 4];
            float av[8] = {a0.x, a0.y, a0.z, a0.w, a1.x, a1.y, a1.z, a1.w};
            float bv[8] = {b0.x, b0.y, b0.z, b0.w, b1.x, b1.y, b1.z, b1.w};
            #pragma unroll
            for (int i = 0; i < 8; i++)
                #pragma unroll
                for (int j = 0; j < 8; j++)
                    acc[i][j] += av[i] * bv[j];
        }
        __syncthreads();
    }

    #pragma unroll
    for (int i = 0; i < 8; i++) {
        int gm = m0 + tr * 8 + i;
        float* orow = out + (size_t)gm * AA + n0 + tc * 8;
        const float* brow = bias + n0 + tc * 8;
        float4 r0, r1;
        r0.x = acc[i][0] + brow[0]; r0.y = acc[i][1] + brow[1];
        r0.z = acc[i][2] + brow[2]; r0.w = acc[i][3] + brow[3];
        r1.x = acc[i][4] + brow[4]; r1.y = acc[i][5] + brow[5];
        r1.z = acc[i][6] + brow[6]; r1.w = acc[i][7] + brow[7];
        *(float4*)orow       = r0;
        *(float4*)(orow + 4) = r1;
    }
}

// ---------------------------------------------------------------------------
// K2: att_dec[m][a] = sum_k dec[m, k] * W_dec[k, a] + b_dec[a]
//     M = 640, N = 512, K = 1024. 64x64x16 tile, 256 threads, 4x4 per thread.
// ---------------------------------------------------------------------------
__global__ __launch_bounds__(256) void k_att_dec(
    const float* __restrict__ dec, const float* __restrict__ W,
    const float* __restrict__ bias, float* __restrict__ out)
{
    __shared__ float As[16][65];   // padded to avoid store conflicts
    __shared__ float Bs[16][64];

    const int m0 = blockIdx.y * 64;
    const int n0 = blockIdx.x * 64;
    const int t  = threadIdx.x;
    const int tr = t >> 4;
    const int tc = t & 15;

    float acc[4][4];
    #pragma unroll
    for (int i = 0; i < 4; i++)
        #pragma unroll
        for (int j = 0; j < 4; j++) acc[i][j] = 0.f;

    for (int k0 = 0; k0 < DD; k0 += 16) {
        #pragma unroll
        for (int i = 0; i < 4; i++) {
            int e = t + i * 256;
            int m = e >> 4, k = e & 15;
            As[k][m] = dec[(size_t)(m0 + m) * DD + k0 + k];
            int kb = e >> 6, n = e & 63;
            Bs[kb][n] = W[(size_t)(k0 + kb) * AA + n0 + n];
        }
        __syncthreads();

        #pragma unroll
        for (int kk = 0; kk < 16; kk++) {
            float av[4], bv[4];
            #pragma unroll
            for (int i = 0; i < 4; i++) av[i] = As[kk][tr * 4 + i];
            #pragma unroll
            for (int j = 0; j < 4; j++) bv[j] = Bs[kk][tc * 4 + j];
            #pragma unroll
            for (int i = 0; i < 4; i++)
                #pragma unroll
                for (int j = 0; j < 4; j++)
                    acc[i][j] += av[i] * bv[j];
        }
        __syncthreads();
    }

    #pragma unroll
    for (int i = 0; i < 4; i++) {
        int gm = m0 + tr * 4 + i;
        #pragma unroll
        for (int j = 0; j < 4; j++) {
            int gn = n0 + tc * 4 + j;
            out[(size_t)gm * AA + gn] = acc[i][j] + bias[gn];
        }
    }
}

// ---------------------------------------------------------------------------
// K3 (fused): per (b,g) block:
//   score[p] = sum_a relu(att_enc[b,p,a] + att_dec[b,g,a]) * w_alpha[a] + b_alpha
//   alpha    = softmax_p(score)        -> written to d_out alpha region
//   att_res[a] = sum_p alpha[p] * att_enc[b,p,a]  -> d_out att_res region
// 256 threads (8 warps). Warp-per-p for scores; thread-per-2a for the sum.
// ---------------------------------------------------------------------------
__global__ __launch_bounds__(256) void k_attend(
    const float* __restrict__ att_enc, const float* __restrict__ att_dec,
    const float* __restrict__ w_alpha, const float* __restrict__ b_alpha,
    float* __restrict__ out_res, float* __restrict__ out_alpha)
{
    const int bg = blockIdx.x;           // 0..639
    const int b = bg / GG;

    __shared__ float sdec[AA];
    __shared__ float sw[AA];
    __shared__ float sscore[PP];
    __shared__ float red[8];

    const int t = threadIdx.x;
    const int warp = t >> 5, lane = t & 31;

    const float* dptr = att_dec + (size_t)bg * AA;
    for (int i = t; i < AA; i += 256) {
        sdec[i] = dptr[i];
        sw[i]   = w_alpha[i];
    }
    __syncthreads();

    const float ba = b_alpha[0];
    const float* eb = att_enc + (size_t)b * PP * AA;

    // --- scores: one warp per pixel ---
    for (int p = warp; p < PP; p += 8) {
        const float* ep = eb + (size_t)p * AA;
        float s = 0.f;
        #pragma unroll
        for (int i = 0; i < AA / 32; i++) {
            int a = lane + i * 32;
            float v = ep[a] + sdec[a];
            s += fmaxf(v, 0.f) * sw[a];
        }
        #pragma unroll
        for (int o = 16; o > 0; o >>= 1)
            s += __shfl_xor_sync(0xffffffffu, s, o);
        if (lane == 0) sscore[p] = s + ba;
    }
    __syncthreads();

    // --- softmax over 196 ---
    float m = -1e30f;
    for (int p = t; p < PP; p += 256) m = fmaxf(m, sscore[p]);
    #pragma unroll
    for (int o = 16; o > 0; o >>= 1)
        m = fmaxf(m, __shfl_xor_sync(0xffffffffu, m, o));
    if (lane == 0) red[warp] = m;
    __syncthreads();
    m = red[0];
    #pragma unroll
    for (int w = 1; w < 8; w++) m = fmaxf(m, red[w]);
    __syncthreads();

    float sum = 0.f;
    for (int p = t; p < PP; p += 256) {
        float ex = __expf(sscore[p] - m);
        sscore[p] = ex;
        sum += ex;
    }
    #pragma unroll
    for (int o = 16; o > 0; o >>= 1)
        sum += __shfl_xor_sync(0xffffffffu, sum, o);
    if (lane == 0) red[warp] = sum;
    __syncthreads();
    sum = 0.f;
    #pragma unroll
    for (int w = 0; w < 8; w++) sum += red[w];
    const float inv = 1.f / sum;
    __syncthreads();

    for (int p = t; p < PP; p += 256) sscore[p] *= inv;
    __syncthreads();

    // write alpha
    float* ao = out_alpha + (size_t)bg * PP;
    for (int p = t; p < PP; p += 256) ao[p] = sscore[p];

    // --- weighted sum over pixels: thread handles a = t and a = t+256 ---
    float acc0 = 0.f, acc1 = 0.f;
    for (int p = 0; p < PP; p++) {
        float al = sscore[p];
        const float* ep = eb + (size_t)p * AA;
        acc0 += al * ep[t];
        acc1 += al * ep[t + 256];
    }
    float* ro = out_res + (size_t)bg * AA;
    ro[t]       = acc0;
    ro[t + 256] = acc1;
}

// ---------------------------------------------------------------------------
extern "C" void kernel_launch(void* const* d_in, const int* in_sizes, int n_in,
                              void* d_out, int out_size)
{
    const float* enc     = (const float*)d_in[0];
    const float* dec     = (const float*)d_in[1];
    const float* W_enc   = (const float*)d_in[2];
    const float* b_enc   = (const float*)d_in[3];
    const float* W_dec   = (const float*)d_in[4];
    const float* b_dec   = (const float*)d_in[5];
    const float* w_alpha = (const float*)d_in[6];
    const float* b_alpha = (const float*)d_in[7];

    float* out = (float*)d_out;
    float* out_res   = out;                        // (B, G, A) = 327680 floats
    float* out_alpha = out + BATCH * GG * AA;      // (B, G, P) = 125440 floats

    float* att_enc_ptr = nullptr;
    float* att_dec_ptr = nullptr;
    cudaGetSymbolAddress((void**)&att_enc_ptr, g_att_enc);
    cudaGetSymbolAddress((void**)&att_dec_ptr, g_att_dec);

    // K1: att_enc  M=6272 N=512 K=2048
    {
        dim3 grid(AA / 128, (BATCH * PP) / 128);   // (4, 49)
        k_att_enc<<<grid, 256>>>(enc, W_enc, b_enc, att_enc_ptr);
    }
    // K2: att_dec  M=640 N=512 K=1024
    {
        dim3 grid(AA / 64, (BATCH * GG) / 64);     // (8, 10)
        k_att_dec<<<grid, 256>>>(dec, W_dec, b_dec, att_dec_ptr);
    }
    // K3: fused score + softmax + weighted sum
    {
        k_attend<<<BATCH * GG, 256>>>(att_enc_ptr, att_dec_ptr,
                                      w_alpha, b_alpha, out_res, out_alpha);
    }
}

// round 3
// speedup vs baseline: 1.6275x; 1.6275x over previous
#include <cuda_runtime.h>
#include <cuda_fp16.h>
#include <cstdint>

// Problem constants
#define BATCH 32
#define CC 2048       // channels (K of GEMM1)
#define PP 196        // H*W
#define GG 20         // decoder steps
#define DD 1024       // decode size (K of GEMM2)
#define AA 512        // att size (N of both GEMMs)

#define M1 (BATCH*PP)      // 6272 = 49*128
#define MT1 49
#define M2 (BATCH*GG)      // 640 = 5*128
#define MT2 5
#define KSEC1 64           // 2048/32 k-chunks per section (GEMM1)
#define KSEC2 32           // 1024/32 (GEMM2)

// MMA GEMM tiling: CTA 128x128, 8 warps (2x4), warp 64x32, chunk K=32
#define STAGES 4
#define CHUNK_BYTES 8192          // 128 rows x 32 k x 2B
#define SROW 80                   // smem row pitch bytes (32*2 + 16 pad)
#define STAGE_BYTES (2*128*SROW)  // A tile + B tile = 20480
#define SMEM_GEMM (STAGES*STAGE_BYTES)   // 81920

// ---------------------------------------------------------------------------
// Scratch (device globals; chunk layout: [tile][chunk][128 rows][32 k] fp16)
// A store: [mt][2*KSEC chunks] (first KSEC = hi, next KSEC = lo)
// B store: [nt][2*KSEC chunks]
// ---------------------------------------------------------------------------
__device__ __align__(16) __half g_A1[MT1 * 2*KSEC1 * 4096];   // 51.4 MB
__device__ __align__(16) __half g_B1[4   * 2*KSEC1 * 4096];   // 4.2 MB
__device__ __align__(16) __half g_A2[MT2 * 2*KSEC2 * 4096];
__device__ __align__(16) __half g_B2[4   * 2*KSEC2 * 4096];
__device__ float g_att_enc[M1*AA];     // (B,P,A) fp32
__device__ float g_att_dec[M2*AA];     // (B,G,A) fp32
__device__ float g_score[M2*PP];       // (B,G,P)

// ---------------------------------------------------------------------------
__device__ __forceinline__ uint32_t smem_u32(const void* p) {
    uint32_t a;
    asm("{ .reg .u64 t; cvta.to.shared.u64 t, %1; cvt.u32.u64 %0, t; }" : "=r"(a) : "l"(p));
    return a;
}
__device__ __forceinline__ void split_h(float x, __half& h, __half& l) {
    h = __float2half_rn(x);
    l = __float2half_rn(x - __half2float(h));
}
__device__ __forceinline__ void cp16(uint32_t saddr, const void* gaddr) {
    asm volatile("cp.async.cg.shared.global [%0], [%1], 16;" :: "r"(saddr), "l"(gaddr));
}
__device__ __forceinline__ void ldm_x4(uint32_t* r, uint32_t addr) {
    asm volatile("ldmatrix.sync.aligned.m8n8.x4.shared.b16 {%0,%1,%2,%3}, [%4];"
        : "=r"(r[0]), "=r"(r[1]), "=r"(r[2]), "=r"(r[3]) : "r"(addr));
}
__device__ __forceinline__ void mma16816(float* c, const uint32_t* a, uint32_t b0, uint32_t b1) {
    asm volatile("mma.sync.aligned.m16n8k16.row.col.f32.f16.f16.f32 "
        "{%0,%1,%2,%3}, {%4,%5,%6,%7}, {%8,%9}, {%0,%1,%2,%3};"
        : "+f"(c[0]), "+f"(c[1]), "+f"(c[2]), "+f"(c[3])
        : "r"(a[0]), "r"(a[1]), "r"(a[2]), "r"(a[3]), "r"(b0), "r"(b1));
}

// ---------------------------------------------------------------------------
// Prep kernels -> chunk layout [128 rows][32 k] fp16, hi + lo chunks.
// ---------------------------------------------------------------------------
// enc (B,C,P): row m = b*196+p, k = c (transpose).  grid (KSEC1, MT1)
__global__ __launch_bounds__(256) void k_prep_A_enc(
    const float* __restrict__ enc, __half* __restrict__ Ast)
{
    __shared__ float sm[32 * 129];
    const int kc = blockIdx.x, mt = blockIdx.y;
    const int t = threadIdx.x;
    #pragma unroll
    for (int i = 0; i < 16; i++) {
        int idx = t + i * 256;            // 4096 = 32c x 128m
        int cl = idx >> 7, ml = idx & 127;
        int m = mt * 128 + ml;
        int b = m / PP, p = m - b * PP;
        sm[cl * 129 + ml] = enc[((size_t)b * CC + (kc * 32 + cl)) * PP + p];
    }
    __syncthreads();
    __half2* hiC = (__half2*)(Ast + ((size_t)mt * 2*KSEC1 + kc) * 4096);
    __half2* loC = (__half2*)(Ast + ((size_t)mt * 2*KSEC1 + kc + KSEC1) * 4096);
    #pragma unroll
    for (int i = 0; i < 8; i++) {
        int e2 = t + i * 256;             // 2048 half2 = 128r x 16
        int row = e2 >> 4, cp = e2 & 15;
        float x0 = sm[(2*cp)   * 129 + row];
        float x1 = sm[(2*cp+1) * 129 + row];
        __half h0, l0, h1, l1;
        split_h(x0, h0, l0); split_h(x1, h1, l1);
        hiC[row * 16 + cp] = __halves2half2(h0, h1);
        loC[row * 16 + cp] = __halves2half2(l0, l1);
    }
}

// W (K, 512): row n = a-col, k (transpose).  grid (kSec, 4)
__global__ __launch_bounds__(256) void k_prep_B(
    const float* __restrict__ W, __half* __restrict__ Bst, int kSec)
{
    __shared__ float sm[32 * 129];
    const int kc = blockIdx.x, nb = blockIdx.y;
    const int t = threadIdx.x;
    #pragma unroll
    for (int i = 0; i < 16; i++) {
        int idx = t + i * 256;
        int kl = idx >> 7, nl = idx & 127;
        sm[kl * 129 + nl] = W[(size_t)(kc * 32 + kl) * AA + nb * 128 + nl];
    }
    __syncthreads();
    __half2* hiC = (__half2*)(Bst + ((size_t)nb * 2*kSec + kc) * 4096);
    __half2* loC = (__half2*)(Bst + ((size_t)nb * 2*kSec + kc + kSec) * 4096);
    #pragma unroll
    for (int i = 0; i < 8; i++) {
        int e2 = t + i * 256;
        int row = e2 >> 4, cp = e2 & 15;
        float x0 = sm[(2*cp)   * 129 + row];
        float x1 = sm[(2*cp+1) * 129 + row];
        __half h0, l0, h1, l1;
        split_h(x0, h0, l0); split_h(x1, h1, l1);
        hiC[row * 16 + cp] = __halves2half2(h0, h1);
        loC[row * 16 + cp] = __halves2half2(l0, l1);
    }
}

// dec (640, 1024) row-major, no transpose.  grid (KSEC2, MT2)
__global__ __launch_bounds__(256) void k_prep_A_dec(
    const float* __restrict__ dec, __half* __restrict__ Ast)
{
    const int kc = blockIdx.x, mt = blockIdx.y;
    const int t = threadIdx.x;
    __half2* hiC = (__half2*)(Ast + ((size_t)mt * 2*KSEC2 + kc) * 4096);
    __half2* loC = (__half2*)(Ast + ((size_t)mt * 2*KSEC2 + kc + KSEC2) * 4096);
    #pragma unroll
    for (int i = 0; i < 8; i++) {
        int e2 = t + i * 256;
        int row = e2 >> 4, cp = e2 & 15;
        const float* src = dec + (size_t)(mt * 128 + row) * DD + kc * 32 + 2*cp;
        float x0 = src[0], x1 = src[1];
        __half h0, l0, h1, l1;
        split_h(x0, h0, l0); split_h(x1, h1, l1);
        hiC[row * 16 + cp] = __halves2half2(h0, h1);
        loC[row * 16 + cp] = __halves2half2(l0, l1);
    }
}

// ---------------------------------------------------------------------------
// fp16 mma.sync GEMM with fp32-emulation via K-section remap.
// K loop runs KC = 3*kSec chunks: s0 Ah*Bh, s1 Ah*Bl, s2 Al*Bh.
// grid (4, MT), 256 threads.
// ---------------------------------------------------------------------------
__global__ __launch_bounds__(256, 2) void k_mma16(
    const __half* __restrict__ Ast, const __half* __restrict__ Bst,
    const float* __restrict__ bias, float* __restrict__ out, int kSec)
{
    extern __shared__ __align__(16) char smem[];
    const int KC = 3 * kSec;
    const int t = threadIdx.x;
    const int lane = t & 31, wid = t >> 5;
    const int wm = wid >> 2, wn = wid & 3;        // warp tile: (wm*64, wn*32)
    const int mt = blockIdx.y, nt = blockIdx.x;

    const char* Abase = (const char*)(Ast + (size_t)mt * 2*kSec * 4096);
    const char* Bbase = (const char*)(Bst + (size_t)nt * 2*kSec * 4096);

    // per-thread cp.async indices: u in {t, t+256}; row = u/4, 16B-chunk = u%4
    const uint32_t smem_base = smem_u32(smem);

    auto issue = [&](int kc) {
        const int s = kc & (STAGES - 1);
        const int akc = (kc < kSec) ? kc : kc - kSec;              // [Ah|Al]
        const int bkc = (kc < 2*kSec) ? kc : kc - 2*kSec;          // [Bh|Bl]
        const char* ga = Abase + (size_t)akc * CHUNK_BYTES;
        const char* gb = Bbase + (size_t)bkc * CHUNK_BYTES;
        const uint32_t sa = smem_base + s * STAGE_BYTES;
        const uint32_t sb = sa + 128 * SROW;
        #pragma unroll
        for (int j = 0; j < 2; j++) {
            int u = t + j * 256;
            int row = u >> 2, c16 = u & 3;
            cp16(sa + row * SROW + c16 * 16, ga + u * 16);
            cp16(sb + row * SROW + c16 * 16, gb + u * 16);
        }
        asm volatile("cp.async.commit_group;");
    };

    issue(0); issue(1); issue(2);

    float c[4][4][4];
    #pragma unroll
    for (int mi = 0; mi < 4; mi++)
        #pragma unroll
        for (int nj = 0; nj < 4; nj++)
            #pragma unroll
            for (int q = 0; q < 4; q++) c[mi][nj][q] = 0.f;

    for (int kc = 0; kc < KC; kc++) {
        asm volatile("cp.async.wait_group 2;");
        __syncthreads();
        const int s = kc & (STAGES - 1);
        const uint32_t sa = smem_base + s * STAGE_BYTES;
        const uint32_t sb = sa + 128 * SROW;
        // ldmatrix base addresses
        const uint32_t aB = sa + (wm * 64 + (lane & 15)) * SROW + (lane >> 4) * 16;
        const uint32_t bB = sb + (wn * 32 + (lane & 15)) * SROW + (lane >> 4) * 16;
        #pragma unroll
        for (int ks = 0; ks < 2; ks++) {
            const uint32_t ko = ks * 32;
            uint32_t a[4][4], bf[2][4];
            #pragma unroll
            for (int mi = 0; mi < 4; mi++) ldm_x4(a[mi], aB + mi * 16 * SROW + ko);
            #pragma unroll
            for (int nj = 0; nj < 2; nj++) ldm_x4(bf[nj], bB + nj * 16 * SROW + ko);
            #pragma unroll
            for (int mi = 0; mi < 4; mi++)
                #pragma unroll
                for (int n8 = 0; n8 < 4; n8++) {
                    const int nj = n8 >> 1, hl = n8 & 1;
                    mma16816(c[mi][n8], a[mi], bf[nj][hl], bf[nj][hl + 2]);
                }
        }
        if (kc + 3 < KC) issue(kc + 3);
        else asm volatile("cp.async.commit_group;");
    }

    // epilogue
    const int r0b = mt * 128 + wm * 64 + (lane >> 2);
    const int ncb = nt * 128 + wn * 32 + (lane & 3) * 2;
    #pragma unroll
    for (int mi = 0; mi < 4; mi++) {
        #pragma unroll
        for (int n8 = 0; n8 < 4; n8++) {
            const int n = ncb + n8 * 8;
            const float b0 = bias[n], b1 = bias[n + 1];
            float* p0 = out + (size_t)(r0b + mi * 16) * AA + n;
            float* p1 = p0 + 8 * AA;
            float2 v0 = { c[mi][n8][0] + b0, c[mi][n8][1] + b1 };
            float2 v1 = { c[mi][n8][2] + b0, c[mi][n8][3] + b1 };
            *(float2*)p0 = v0;
            *(float2*)p1 = v1;
        }
    }
}

// ---------------------------------------------------------------------------
// K3a: scores. Block = (p-tile of 8 warps, b). att_enc row reused across 20 g.
// ---------------------------------------------------------------------------
__global__ __launch_bounds__(256) void k_score(
    const float* __restrict__ w_alpha, const float* __restrict__ b_alpha,
    float* __restrict__ score)
{
    __shared__ float sdec[GG * AA];   // 40KB
    __shared__ float sw_[AA];
    const int b = blockIdx.y;
    const int t = threadIdx.x, warp = t >> 5, lane = t & 31;

    const float* dptr = g_att_dec + (size_t)b * GG * AA;
    for (int i = t; i < GG * AA; i += 256) sdec[i] = dptr[i];
    for (int i = t; i < AA; i += 256) sw_[i] = w_alpha[i];
    __syncthreads();

    const int p = blockIdx.x * 8 + warp;
    if (p >= PP) return;
    const float ba = b_alpha[0];
    const float* ep = g_att_enc + ((size_t)b * PP + p) * AA;

    float e[16];
    #pragma unroll
    for (int i = 0; i < 16; i++) e[i] = ep[lane + 32 * i];

    for (int g = 0; g < GG; g++) {
        float s = 0.f;
        const float* dg = sdec + g * AA;
        #pragma unroll
        for (int i = 0; i < 16; i++) {
            int a = lane + 32 * i;
            float v = e[i] + dg[a];
            s = fmaf(fmaxf(v, 0.f), sw_[a], s);
        }
        #pragma unroll
        for (int o = 16; o > 0; o >>= 1)
            s += __shfl_xor_sync(0xffffffffu, s, o);
        if (lane == 0) score[((size_t)b * GG + g) * PP + p] = s + ba;
    }
}

// ---------------------------------------------------------------------------
// K3b: softmax over 196, writes alpha to output
// ---------------------------------------------------------------------------
__global__ __launch_bounds__(256) void k_softmax(
    const float* __restrict__ score, float* __restrict__ out_alpha)
{
    const int bg = blockIdx.x;
    __shared__ float ss[PP];
    __shared__ float red[8];
    const int t = threadIdx.x, warp = t >> 5, lane = t & 31;

    for (int p = t; p < PP; p += 256) ss[p] = score[(size_t)bg * PP + p];
    __syncthreads();

    float m = -1e30f;
    for (int p = t; p < PP; p += 256) m = fmaxf(m, ss[p]);
    #pragma unroll
    for (int o = 16; o > 0; o >>= 1) m = fmaxf(m, __shfl_xor_sync(0xffffffffu, m, o));
    if (lane == 0) red[warp] = m;
    __syncthreads();
    m = red[0];
    #pragma unroll
    for (int w = 1; w < 8; w++) m = fmaxf(m, red[w]);
    __syncthreads();

    float sum = 0.f;
    for (int p = t; p < PP; p += 256) {
        float ex = __expf(ss[p] - m);
        ss[p] = ex;
        sum += ex;
    }
    #pragma unroll
    for (int o = 16; o > 0; o >>= 1) sum += __shfl_xor_sync(0xffffffffu, sum, o);
    if (lane == 0) red[warp] = sum;
    __syncthreads();
    sum = 0.f;
    #pragma unroll
    for (int w = 0; w < 8; w++) sum += red[w];
    const float inv = 1.f / sum;
    __syncthreads();

    float* ao = out_alpha + (size_t)bg * PP;
    for (int p = t; p < PP; p += 256) ao[p] = ss[p] * inv;
}

// ---------------------------------------------------------------------------
// K3c: att_res[b,g,:] = sum_p alpha[b,g,p] * att_enc[b,p,:]
// ---------------------------------------------------------------------------
__global__ __launch_bounds__(256) void k_wsum(
    const float* __restrict__ alpha, float* __restrict__ out_res)
{
    __shared__ float sal[GG * PP];
    const int b = blockIdx.y, a0 = blockIdx.x * 128;
    const int t = threadIdx.x;
    const float* ap = alpha + (size_t)b * GG * PP;
    for (int i = t; i < GG * PP; i += 256) sal[i] = ap[i];
    __syncthreads();

    const int al = t & 127, h = t >> 7;
    float acc[10];
    #pragma unroll
    for (int j = 0; j < 10; j++) acc[j] = 0.f;

    const float* eb = g_att_enc + (size_t)b * PP * AA + a0 + al;
    for (int p = 0; p < PP; p++) {
        float v = eb[(size_t)p * AA];
        #pragma unroll
        for (int j = 0; j < 10; j++)
            acc[j] = fmaf(sal[(h * 10 + j) * PP + p], v, acc[j]);
    }
    #pragma unroll
    for (int j = 0; j < 10; j++)
        out_res[((size_t)b * GG + h * 10 + j) * AA + a0 + al] = acc[j];
}

// ---------------------------------------------------------------------------
extern "C" void kernel_launch(void* const* d_in, const int* in_sizes, int n_in,
                              void* d_out, int out_size)
{
    const float* enc     = (const float*)d_in[0];
    const float* dec     = (const float*)d_in[1];
    const float* W_enc   = (const float*)d_in[2];
    const float* b_enc   = (const float*)d_in[3];
    const float* W_dec   = (const float*)d_in[4];
    const float* b_dec   = (const float*)d_in[5];
    const float* w_alpha = (const float*)d_in[6];
    const float* b_alpha = (const float*)d_in[7];

    float* out = (float*)d_out;
    float* out_res   = out;                        // (B,G,A)
    float* out_alpha = out + (size_t)M2 * AA;      // (B,G,P)

    __half *A1, *B1, *A2, *B2;
    float *att_enc, *att_dec, *score;
    cudaGetSymbolAddress((void**)&A1, g_A1);
    cudaGetSymbolAddress((void**)&B1, g_B1);
    cudaGetSymbolAddress((void**)&A2, g_A2);
    cudaGetSymbolAddress((void**)&B2, g_B2);
    cudaGetSymbolAddress((void**)&att_enc, g_att_enc);
    cudaGetSymbolAddress((void**)&att_dec, g_att_dec);
    cudaGetSymbolAddress((void**)&score, g_score);

    static bool attr_done = false;
    if (!attr_done) {
        cudaFuncSetAttribute(k_mma16, cudaFuncAttributeMaxDynamicSharedMemorySize, SMEM_GEMM);
        attr_done = true;
    }

    // prep: fp32 -> fp16 hi/lo chunked tiles
    k_prep_A_enc<<<dim3(KSEC1, MT1), 256>>>(enc, A1);
    k_prep_B    <<<dim3(KSEC1, 4),   256>>>(W_enc, B1, KSEC1);
    k_prep_A_dec<<<dim3(KSEC2, MT2), 256>>>(dec, A2);
    k_prep_B    <<<dim3(KSEC2, 4),   256>>>(W_dec, B2, KSEC2);

    // GEMMs on mma.sync fp16 (3-product fp32 emulation)
    k_mma16<<<dim3(4, MT1), 256, SMEM_GEMM>>>(A1, B1, b_enc, att_enc, KSEC1);
    k_mma16<<<dim3(4, MT2), 256, SMEM_GEMM>>>(A2, B2, b_dec, att_dec, KSEC2);

    // attention tail
    k_score  <<<dim3(25, BATCH), 256>>>(w_alpha, b_alpha, score);
    k_softmax<<<M2, 256>>>(score, out_alpha);
    k_wsum   <<<dim3(4, BATCH), 256>>>(out_alpha, out_res);
}

// round 4
// speedup vs baseline: 2.3118x; 1.4205x over previous
#include <cuda_runtime.h>
#include <cuda_fp16.h>
#include <cstdint>

// Problem constants
#define BATCH 32
#define CC 2048       // channels (K of GEMM1)
#define PP 196        // H*W
#define GG 20         // decoder steps
#define DD 1024       // decode size (K of GEMM2)
#define AA 512        // att size (N of both GEMMs)

#define M1 (BATCH*PP)      // 6272 = 49*128
#define MT1 49
#define M2 (BATCH*GG)      // 640 = 5*128
#define MT2 5
#define KSEC1 64           // 2048/32 k-chunks (GEMM1)
#define KSEC2 32           // 1024/32 (GEMM2)

// GEMM tiling: CTA 128x128, 8 warps (2x4), warp 64x32, chunk K=32
// Stage = {Ah, Bh, Bl} subtiles, each 128 rows x 32 k fp16, 80B pitch.
#define STAGES 3
#define CHUNK_BYTES 8192          // 128 x 32 x 2B (global, unpadded)
#define SROW 80                   // smem row pitch (64B data + 16B pad)
#define SUBT (128*SROW)           // 10240
#define STAGE_BYTES (3*SUBT)      // 30720
#define SMEM_GEMM (STAGES*STAGE_BYTES)   // 92160

// ---------------------------------------------------------------------------
// Scratch. A: hi only, [mt][kc][128x32]. B: [nt][kc hi | kc+kSec lo][128x32].
// ---------------------------------------------------------------------------
__device__ __align__(16) __half g_A1[MT1 * KSEC1 * 4096];     // 25.7 MB
__device__ __align__(16) __half g_B1[4   * 2*KSEC1 * 4096];   // 4.2 MB
__device__ __align__(16) __half g_A2[MT2 * KSEC2 * 4096];
__device__ __align__(16) __half g_B2[4   * 2*KSEC2 * 4096];
__device__ float g_att_enc[M1*AA];     // (B,P,A) fp32
__device__ float g_att_dec[M2*AA];     // (B,G,A) fp32
__device__ float g_score[M2*PP];       // (B,G,P)

// ---------------------------------------------------------------------------
__device__ __forceinline__ uint32_t smem_u32(const void* p) {
    uint32_t a;
    asm("{ .reg .u64 t; cvta.to.shared.u64 t, %1; cvt.u32.u64 %0, t; }" : "=r"(a) : "l"(p));
    return a;
}
__device__ __forceinline__ void split_h(float x, __half& h, __half& l) {
    h = __float2half_rn(x);
    l = __float2half_rn(x - __half2float(h));
}
__device__ __forceinline__ void cp16(uint32_t saddr, const void* gaddr) {
    asm volatile("cp.async.cg.shared.global [%0], [%1], 16;" :: "r"(saddr), "l"(gaddr));
}
__device__ __forceinline__ void ldm_x4(uint32_t* r, uint32_t addr) {
    asm volatile("ldmatrix.sync.aligned.m8n8.x4.shared.b16 {%0,%1,%2,%3}, [%4];"
        : "=r"(r[0]), "=r"(r[1]), "=r"(r[2]), "=r"(r[3]) : "r"(addr));
}
__device__ __forceinline__ void mma16816(float* c, const uint32_t* a, uint32_t b0, uint32_t b1) {
    asm volatile("mma.sync.aligned.m16n8k16.row.col.f32.f16.f16.f32 "
        "{%0,%1,%2,%3}, {%4,%5,%6,%7}, {%8,%9}, {%0,%1,%2,%3};"
        : "+f"(c[0]), "+f"(c[1]), "+f"(c[2]), "+f"(c[3])
        : "r"(a[0]), "r"(a[1]), "r"(a[2]), "r"(a[3]), "r"(b0), "r"(b1));
}

// ---------------------------------------------------------------------------
// Prep kernels
// ---------------------------------------------------------------------------
// enc (B,C,P): row m = b*196+p, k = c (transpose), fp16 hi only. grid (KSEC1, MT1)
__global__ __launch_bounds__(256) void k_prep_A_enc(
    const float* __restrict__ enc, __half* __restrict__ Ast)
{
    __shared__ float sm[32 * 129];
    const int kc = blockIdx.x, mt = blockIdx.y;
    const int t = threadIdx.x;
    #pragma unroll
    for (int i = 0; i < 16; i++) {
        int idx = t + i * 256;            // 4096 = 32c x 128m
        int cl = idx >> 7, ml = idx & 127;
        int m = mt * 128 + ml;
        int b = m / PP, p = m - b * PP;
        sm[cl * 129 + ml] = enc[((size_t)b * CC + (kc * 32 + cl)) * PP + p];
    }
    __syncthreads();
    __half2* hiC = (__half2*)(Ast + ((size_t)mt * KSEC1 + kc) * 4096);
    #pragma unroll
    for (int i = 0; i < 8; i++) {
        int e2 = t + i * 256;             // 2048 half2 = 128r x 16
        int row = e2 >> 4, cp = e2 & 15;
        float x0 = sm[(2*cp)   * 129 + row];
        float x1 = sm[(2*cp+1) * 129 + row];
        hiC[row * 16 + cp] = __halves2half2(__float2half_rn(x0), __float2half_rn(x1));
    }
}

// W (K, 512): row n = a-col, k (transpose), hi + lo chunks. grid (kSec, 4)
__global__ __launch_bounds__(256) void k_prep_B(
    const float* __restrict__ W, __half* __restrict__ Bst, int kSec)
{
    __shared__ float sm[32 * 129];
    const int kc = blockIdx.x, nb = blockIdx.y;
    const int t = threadIdx.x;
    #pragma unroll
    for (int i = 0; i < 16; i++) {
        int idx = t + i * 256;
        int kl = idx >> 7, nl = idx & 127;
        sm[kl * 129 + nl] = W[(size_t)(kc * 32 + kl) * AA + nb * 128 + nl];
    }
    __syncthreads();
    __half2* hiC = (__half2*)(Bst + ((size_t)nb * 2*kSec + kc) * 4096);
    __half2* loC = (__half2*)(Bst + ((size_t)nb * 2*kSec + kc + kSec) * 4096);
    #pragma unroll
    for (int i = 0; i < 8; i++) {
        int e2 = t + i * 256;
        int row = e2 >> 4, cp = e2 & 15;
        float x0 = sm[(2*cp)   * 129 + row];
        float x1 = sm[(2*cp+1) * 129 + row];
        __half h0, l0, h1, l1;
        split_h(x0, h0, l0); split_h(x1, h1, l1);
        hiC[row * 16 + cp] = __halves2half2(h0, h1);
        loC[row * 16 + cp] = __halves2half2(l0, l1);
    }
}

// dec (640, 1024) row-major, fp16 hi only. grid (KSEC2, MT2)
__global__ __launch_bounds__(256) void k_prep_A_dec(
    const float* __restrict__ dec, __half* __restrict__ Ast)
{
    const int kc = blockIdx.x, mt = blockIdx.y;
    const int t = threadIdx.x;
    __half2* hiC = (__half2*)(Ast + ((size_t)mt * KSEC2 + kc) * 4096);
    #pragma unroll
    for (int i = 0; i < 8; i++) {
        int e2 = t + i * 256;
        int row = e2 >> 4, cp = e2 & 15;
        const float* src = dec + (size_t)(mt * 128 + row) * DD + kc * 32 + 2*cp;
        hiC[row * 16 + cp] = __halves2half2(__float2half_rn(src[0]), __float2half_rn(src[1]));
    }
}

// ---------------------------------------------------------------------------
// fp16 mma.sync GEMM, 2-product emulation: C = Ah*Bh + Ah*Bl (+bias)
// One stage per k-chunk holds {Ah, Bh, Bl}; kSec iterations; grid (4, MT).
// ---------------------------------------------------------------------------
__global__ __launch_bounds__(256, 2) void k_mma16(
    const __half* __restrict__ Ast, const __half* __restrict__ Bst,
    const float* __restrict__ bias, float* __restrict__ out, int kSec)
{
    extern __shared__ __align__(16) char smem[];
    const int t = threadIdx.x;
    const int lane = t & 31, wid = t >> 5;
    const int wm = wid >> 2, wn = wid & 3;        // warp tile (wm*64, wn*32)
    const int mt = blockIdx.y, nt = blockIdx.x;

    const char* Abase = (const char*)(Ast + (size_t)mt * kSec * 4096);
    const char* Bbase = (const char*)(Bst + (size_t)nt * 2*kSec * 4096);
    const uint32_t smem_base = smem_u32(smem);

    auto issue = [&](int kc) {
        const int s = kc % STAGES;
        const char* ga  = Abase + (size_t)kc * CHUNK_BYTES;
        const char* gbh = Bbase + (size_t)kc * CHUNK_BYTES;
        const char* gbl = Bbase + (size_t)(kc + kSec) * CHUNK_BYTES;
        const uint32_t st = smem_base + s * STAGE_BYTES;
        #pragma unroll
        for (int j = 0; j < 2; j++) {
            int u = t + j * 256;          // 512 16B-chunks per subtile
            int r = u >> 2, c = u & 3;
            uint32_t d = r * SROW + c * 16;
            cp16(st + d,            ga  + u * 16);
            cp16(st + SUBT + d,     gbh + u * 16);
            cp16(st + 2*SUBT + d,   gbl + u * 16);
        }
        asm volatile("cp.async.commit_group;");
    };

    issue(0); issue(1);

    float c[4][4][4];
    #pragma unroll
    for (int mi = 0; mi < 4; mi++)
        #pragma unroll
        for (int nj = 0; nj < 4; nj++)
            #pragma unroll
            for (int q = 0; q < 4; q++) c[mi][nj][q] = 0.f;

    for (int kc = 0; kc < kSec; kc++) {
        asm volatile("cp.async.wait_group 1;");
        __syncthreads();
        const int s = kc % STAGES;
        const uint32_t st = smem_base + s * STAGE_BYTES;
        const uint32_t aB = st + (wm * 64 + (lane & 15)) * SROW + (lane >> 4) * 16;
        const uint32_t bB = st + SUBT + (wn * 32 + (lane & 15)) * SROW + (lane >> 4) * 16;
        #pragma unroll
        for (int ks = 0; ks < 2; ks++) {
            const uint32_t ko = ks * 32;
            uint32_t a[4][4], bh[2][4], bl[2][4];
            #pragma unroll
            for (int mi = 0; mi < 4; mi++) ldm_x4(a[mi], aB + mi * 16 * SROW + ko);
            #pragma unroll
            for (int nj = 0; nj < 2; nj++) {
                ldm_x4(bh[nj], bB + nj * 16 * SROW + ko);
                ldm_x4(bl[nj], bB + SUBT + nj * 16 * SROW + ko);
            }
            #pragma unroll
            for (int mi = 0; mi < 4; mi++)
                #pragma unroll
                for (int n8 = 0; n8 < 4; n8++) {
                    const int nj = n8 >> 1, hl = n8 & 1;
                    mma16816(c[mi][n8], a[mi], bh[nj][hl], bh[nj][hl + 2]);
                    mma16816(c[mi][n8], a[mi], bl[nj][hl], bl[nj][hl + 2]);
                }
        }
        if (kc + 2 < kSec) issue(kc + 2);
        else asm volatile("cp.async.commit_group;");
    }

    // epilogue
    const int r0b = mt * 128 + wm * 64 + (lane >> 2);
    const int ncb = nt * 128 + wn * 32 + (lane & 3) * 2;
    #pragma unroll
    for (int mi = 0; mi < 4; mi++) {
        #pragma unroll
        for (int n8 = 0; n8 < 4; n8++) {
            const int n = ncb + n8 * 8;
            const float b0 = bias[n], b1 = bias[n + 1];
            float* p0 = out + (size_t)(r0b + mi * 16) * AA + n;
            float* p1 = p0 + 8 * AA;
            float2 v0 = { c[mi][n8][0] + b0, c[mi][n8][1] + b1 };
            float2 v1 = { c[mi][n8][2] + b0, c[mi][n8][3] + b1 };
            *(float2*)p0 = v0;
            *(float2*)p1 = v1;
        }
    }
}

// ---------------------------------------------------------------------------
// K3a: scores. Block = (p-tile of 8 warps, b). att_enc row reused across 20 g.
// ---------------------------------------------------------------------------
__global__ __launch_bounds__(256) void k_score(
    const float* __restrict__ w_alpha, const float* __restrict__ b_alpha,
    float* __restrict__ score)
{
    __shared__ float sdec[GG * AA];   // 40KB
    __shared__ float sw_[AA];
    const int b = blockIdx.y;
    const int t = threadIdx.x, warp = t >> 5, lane = t & 31;

    const float* dptr = g_att_dec + (size_t)b * GG * AA;
    for (int i = t; i < GG * AA; i += 256) sdec[i] = dptr[i];
    for (int i = t; i < AA; i += 256) sw_[i] = w_alpha[i];
    __syncthreads();

    const int p = blockIdx.x * 8 + warp;
    if (p >= PP) return;
    const float ba = b_alpha[0];
    const float* ep = g_att_enc + ((size_t)b * PP + p) * AA;

    float e[16];
    #pragma unroll
    for (int i = 0; i < 16; i++) e[i] = ep[lane + 32 * i];

    for (int g = 0; g < GG; g++) {
        float s = 0.f;
        const float* dg = sdec + g * AA;
        #pragma unroll
        for (int i = 0; i < 16; i++) {
            int a = lane + 32 * i;
            float v = e[i] + dg[a];
            s = fmaf(fmaxf(v, 0.f), sw_[a], s);
        }
        #pragma unroll
        for (int o = 16; o > 0; o >>= 1)
            s += __shfl_xor_sync(0xffffffffu, s, o);
        if (lane == 0) score[((size_t)b * GG + g) * PP + p] = s + ba;
    }
}

// ---------------------------------------------------------------------------
// K3b: softmax over 196, writes alpha to output
// ---------------------------------------------------------------------------
__global__ __launch_bounds__(256) void k_softmax(
    const float* __restrict__ score, float* __restrict__ out_alpha)
{
    const int bg = blockIdx.x;
    __shared__ float ss[PP];
    __shared__ float red[8];
    const int t = threadIdx.x, warp = t >> 5, lane = t & 31;

    for (int p = t; p < PP; p += 256) ss[p] = score[(size_t)bg * PP + p];
    __syncthreads();

    float m = -1e30f;
    for (int p = t; p < PP; p += 256) m = fmaxf(m, ss[p]);
    #pragma unroll
    for (int o = 16; o > 0; o >>= 1) m = fmaxf(m, __shfl_xor_sync(0xffffffffu, m, o));
    if (lane == 0) red[warp] = m;
    __syncthreads();
    m = red[0];
    #pragma unroll
    for (int w = 1; w < 8; w++) m = fmaxf(m, red[w]);
    __syncthreads();

    float sum = 0.f;
    for (int p = t; p < PP; p += 256) {
        float ex = __expf(ss[p] - m);
        ss[p] = ex;
        sum += ex;
    }
    #pragma unroll
    for (int o = 16; o > 0; o >>= 1) sum += __shfl_xor_sync(0xffffffffu, sum, o);
    if (lane == 0) red[warp] = sum;
    __syncthreads();
    sum = 0.f;
    #pragma unroll
    for (int w = 0; w < 8; w++) sum += red[w];
    const float inv = 1.f / sum;
    __syncthreads();

    float* ao = out_alpha + (size_t)bg * PP;
    for (int p = t; p < PP; p += 256) ao[p] = ss[p] * inv;
}

// ---------------------------------------------------------------------------
// K3c: att_res[b,g,:] = sum_p alpha[b,g,p] * att_enc[b,p,:]
// ---------------------------------------------------------------------------
__global__ __launch_bounds__(256) void k_wsum(
    const float* __restrict__ alpha, float* __restrict__ out_res)
{
    __shared__ float sal[GG * PP];
    const int b = blockIdx.y, a0 = blockIdx.x * 128;
    const int t = threadIdx.x;
    const float* ap = alpha + (size_t)b * GG * PP;
    for (int i = t; i < GG * PP; i += 256) sal[i] = ap[i];
    __syncthreads();

    const int al = t & 127, h = t >> 7;
    float acc[10];
    #pragma unroll
    for (int j = 0; j < 10; j++) acc[j] = 0.f;

    const float* eb = g_att_enc + (size_t)b * PP * AA + a0 + al;
    for (int p = 0; p < PP; p++) {
        float v = eb[(size_t)p * AA];
        #pragma unroll
        for (int j = 0; j < 10; j++)
            acc[j] = fmaf(sal[(h * 10 + j) * PP + p], v, acc[j]);
    }
    #pragma unroll
    for (int j = 0; j < 10; j++)
        out_res[((size_t)b * GG + h * 10 + j) * AA + a0 + al] = acc[j];
}

// ---------------------------------------------------------------------------
extern "C" void kernel_launch(void* const* d_in, const int* in_sizes, int n_in,
                              void* d_out, int out_size)
{
    const float* enc     = (const float*)d_in[0];
    const float* dec     = (const float*)d_in[1];
    const float* W_enc   = (const float*)d_in[2];
    const float* b_enc   = (const float*)d_in[3];
    const float* W_dec   = (const float*)d_in[4];
    const float* b_dec   = (const float*)d_in[5];
    const float* w_alpha = (const float*)d_in[6];
    const float* b_alpha = (const float*)d_in[7];

    float* out = (float*)d_out;
    float* out_res   = out;                        // (B,G,A)
    float* out_alpha = out + (size_t)M2 * AA;      // (B,G,P)

    __half *A1, *B1, *A2, *B2;
    float *att_enc, *att_dec, *score;
    cudaGetSymbolAddress((void**)&A1, g_A1);
    cudaGetSymbolAddress((void**)&B1, g_B1);
    cudaGetSymbolAddress((void**)&A2, g_A2);
    cudaGetSymbolAddress((void**)&B2, g_B2);
    cudaGetSymbolAddress((void**)&att_enc, g_att_enc);
    cudaGetSymbolAddress((void**)&att_dec, g_att_dec);
    cudaGetSymbolAddress((void**)&score, g_score);

    cudaFuncSetAttribute(k_mma16, cudaFuncAttributeMaxDynamicSharedMemorySize, SMEM_GEMM);

    // prep
    k_prep_A_enc<<<dim3(KSEC1, MT1), 256>>>(enc, A1);
    k_prep_B    <<<dim3(KSEC1, 4),   256>>>(W_enc, B1, KSEC1);
    k_prep_A_dec<<<dim3(KSEC2, MT2), 256>>>(dec, A2);
    k_prep_B    <<<dim3(KSEC2, 4),   256>>>(W_dec, B2, KSEC2);

    // GEMMs (2-product fp16 emulation)
    k_mma16<<<dim3(4, MT1), 256, SMEM_GEMM>>>(A1, B1, b_enc, att_enc, KSEC1);
    k_mma16<<<dim3(4, MT2), 256, SMEM_GEMM>>>(A2, B2, b_dec, att_dec, KSEC2);

    // attention tail
    k_score  <<<dim3(25, BATCH), 256>>>(w_alpha, b_alpha, score);
    k_softmax<<<M2, 256>>>(score, out_alpha);
    k_wsum   <<<dim3(4, BATCH), 256>>>(out_alpha, out_res);
}

// round 5
// speedup vs baseline: 3.6380x; 1.5737x over previous
#include <cuda_runtime.h>
#include <cuda_fp16.h>
#include <cstdint>

// Problem constants
#define BATCH 32
#define CC 2048       // channels (K of GEMM1)
#define PP 196        // H*W
#define GG 20         // decoder steps
#define DD 1024       // decode size (K of GEMM2)
#define AA 512        // att size (N of both GEMMs)

#define M1 (BATCH*PP)      // 6272 = 49*128
#define MT1 49
#define M2 (BATCH*GG)      // 640 = 5*128
#define MT2 5
#define KSEC1 64           // 2048/32 k-chunks (GEMM1)
#define KSEC2 32           // 1024/32 (GEMM2)

// GEMM tiling: CTA 128x64, 4 warps (2x2), warp 64x32, chunk K=32.
// Single-product fp16: C = Ah*Bh (+bias).
#define STAGES 3
#define CHUNK_A 8192              // 128 x 32 x 2B
#define CHUNK_B 4096              // 64 x 32 x 2B
#define SROW 80                   // smem row pitch (64B data + 16B pad)
#define SUBT_A (128*SROW)         // 10240
#define SUBT_B (64*SROW)          // 5120
#define STAGE_BYTES (SUBT_A + SUBT_B)    // 15360
#define SMEM_GEMM (STAGES*STAGE_BYTES)   // 46080

// ---------------------------------------------------------------------------
// Scratch. A: [mt][kc][128x32] fp16. B: [nt(64-wide)][kc][64x32] fp16.
// ---------------------------------------------------------------------------
__device__ __align__(16) __half g_A1[MT1 * KSEC1 * 4096];   // 25.7 MB
__device__ __align__(16) __half g_B1[8   * KSEC1 * 2048];   // 2.1 MB
__device__ __align__(16) __half g_A2[MT2 * KSEC2 * 4096];
__device__ __align__(16) __half g_B2[8   * KSEC2 * 2048];
__device__ float g_att_enc[M1*AA];     // (B,P,A) fp32
__device__ float g_att_dec[M2*AA];     // (B,G,A) fp32
__device__ float g_score[M2*PP];       // (B,G,P)

// ---------------------------------------------------------------------------
__device__ __forceinline__ uint32_t smem_u32(const void* p) {
    uint32_t a;
    asm("{ .reg .u64 t; cvta.to.shared.u64 t, %1; cvt.u32.u64 %0, t; }" : "=r"(a) : "l"(p));
    return a;
}
__device__ __forceinline__ void cp16(uint32_t saddr, const void* gaddr) {
    asm volatile("cp.async.cg.shared.global [%0], [%1], 16;" :: "r"(saddr), "l"(gaddr));
}
__device__ __forceinline__ void ldm_x4(uint32_t* r, uint32_t addr) {
    asm volatile("ldmatrix.sync.aligned.m8n8.x4.shared.b16 {%0,%1,%2,%3}, [%4];"
        : "=r"(r[0]), "=r"(r[1]), "=r"(r[2]), "=r"(r[3]) : "r"(addr));
}
__device__ __forceinline__ void mma16816(float* c, const uint32_t* a, uint32_t b0, uint32_t b1) {
    asm volatile("mma.sync.aligned.m16n8k16.row.col.f32.f16.f16.f32 "
        "{%0,%1,%2,%3}, {%4,%5,%6,%7}, {%8,%9}, {%0,%1,%2,%3};"
        : "+f"(c[0]), "+f"(c[1]), "+f"(c[2]), "+f"(c[3])
        : "r"(a[0]), "r"(a[1]), "r"(a[2]), "r"(a[3]), "r"(b0), "r"(b1));
}

// ---------------------------------------------------------------------------
// Prep kernels (fp32 -> fp16 round-to-nearest, chunked layouts)
// ---------------------------------------------------------------------------
// enc (B,C,P): row m = b*196+p, k = c (transpose). grid (KSEC1, MT1)
__global__ __launch_bounds__(256) void k_prep_A_enc(
    const float* __restrict__ enc, __half* __restrict__ Ast)
{
    __shared__ float sm[32 * 129];
    const int kc = blockIdx.x, mt = blockIdx.y;
    const int t = threadIdx.x;
    #pragma unroll
    for (int i = 0; i < 16; i++) {
        int idx = t + i * 256;            // 4096 = 32c x 128m
        int cl = idx >> 7, ml = idx & 127;
        int m = mt * 128 + ml;
        int b = m / PP, p = m - b * PP;
        sm[cl * 129 + ml] = enc[((size_t)b * CC + (kc * 32 + cl)) * PP + p];
    }
    __syncthreads();
    __half2* hiC = (__half2*)(Ast + ((size_t)mt * KSEC1 + kc) * 4096);
    #pragma unroll
    for (int i = 0; i < 8; i++) {
        int e2 = t + i * 256;             // 2048 half2 = 128r x 16
        int row = e2 >> 4, cp = e2 & 15;
        float x0 = sm[(2*cp)   * 129 + row];
        float x1 = sm[(2*cp+1) * 129 + row];
        hiC[row * 16 + cp] = __halves2half2(__float2half_rn(x0), __float2half_rn(x1));
    }
}

// W (K, 512): row n, k (transpose); 64-row n-tiles. grid (kSec, 4): block covers 128 n.
__global__ __launch_bounds__(256) void k_prep_B(
    const float* __restrict__ W, __half* __restrict__ Bst, int kSec)
{
    __shared__ float sm[32 * 129];
    const int kc = blockIdx.x, nb = blockIdx.y;
    const int t = threadIdx.x;
    #pragma unroll
    for (int i = 0; i < 16; i++) {
        int idx = t + i * 256;
        int kl = idx >> 7, nl = idx & 127;
        sm[kl * 129 + nl] = W[(size_t)(kc * 32 + kl) * AA + nb * 128 + nl];
    }
    __syncthreads();
    #pragma unroll
    for (int i = 0; i < 8; i++) {
        int e2 = t + i * 256;             // 2048 half2 = 128 n-rows x 16
        int row = e2 >> 4, cp = e2 & 15;  // row = n within 128-block
        float x0 = sm[(2*cp)   * 129 + row];
        float x1 = sm[(2*cp+1) * 129 + row];
        int nt = nb * 2 + (row >> 6);
        int rl = row & 63;
        __half2* dst = (__half2*)(Bst + ((size_t)nt * kSec + kc) * 2048);
        dst[rl * 16 + cp] = __halves2half2(__float2half_rn(x0), __float2half_rn(x1));
    }
}

// dec (640, 1024) row-major. grid (KSEC2, MT2)
__global__ __launch_bounds__(256) void k_prep_A_dec(
    const float* __restrict__ dec, __half* __restrict__ Ast)
{
    const int kc = blockIdx.x, mt = blockIdx.y;
    const int t = threadIdx.x;
    __half2* hiC = (__half2*)(Ast + ((size_t)mt * KSEC2 + kc) * 4096);
    #pragma unroll
    for (int i = 0; i < 8; i++) {
        int e2 = t + i * 256;
        int row = e2 >> 4, cp = e2 & 15;
        const float* src = dec + (size_t)(mt * 128 + row) * DD + kc * 32 + 2*cp;
        hiC[row * 16 + cp] = __halves2half2(__float2half_rn(src[0]), __float2half_rn(src[1]));
    }
}

// ---------------------------------------------------------------------------
// fp16 mma.sync GEMM, single product. CTA 128x64, 128 threads (2x2 warps of
// 64x32), 3-stage cp.async pipeline. grid (8, MT).
// ---------------------------------------------------------------------------
__global__ __launch_bounds__(128, 3) void k_mma16(
    const __half* __restrict__ Ast, const __half* __restrict__ Bst,
    const float* __restrict__ bias, float* __restrict__ out, int kSec)
{
    extern __shared__ __align__(16) char smem[];
    const int t = threadIdx.x;
    const int lane = t & 31, wid = t >> 5;
    const int wm = wid >> 1, wn = wid & 1;        // warp tile (wm*64, wn*32)
    const int mt = blockIdx.y, nt = blockIdx.x;

    const char* Abase = (const char*)(Ast + (size_t)mt * kSec * 4096);
    const char* Bbase = (const char*)(Bst + (size_t)nt * kSec * 2048);
    const uint32_t smem_base = smem_u32(smem);

    auto issue = [&](int kc) {
        const int s = kc % STAGES;
        const char* ga = Abase + (size_t)kc * CHUNK_A;
        const char* gb = Bbase + (size_t)kc * CHUNK_B;
        const uint32_t st = smem_base + s * STAGE_BYTES;
        #pragma unroll
        for (int j = 0; j < 4; j++) {     // A: 512 16B-chunks
            int u = t + j * 128;
            cp16(st + (u >> 2) * SROW + (u & 3) * 16, ga + u * 16);
        }
        #pragma unroll
        for (int j = 0; j < 2; j++) {     // B: 256 16B-chunks
            int u = t + j * 128;
            cp16(st + SUBT_A + (u >> 2) * SROW + (u & 3) * 16, gb + u * 16);
        }
        asm volatile("cp.async.commit_group;");
    };

    issue(0); issue(1);

    float c[4][4][4];
    #pragma unroll
    for (int mi = 0; mi < 4; mi++)
        #pragma unroll
        for (int nj = 0; nj < 4; nj++)
            #pragma unroll
            for (int q = 0; q < 4; q++) c[mi][nj][q] = 0.f;

    for (int kc = 0; kc < kSec; kc++) {
        asm volatile("cp.async.wait_group 1;");
        __syncthreads();
        const int s = kc % STAGES;
        const uint32_t st = smem_base + s * STAGE_BYTES;
        const uint32_t aB = st + (wm * 64 + (lane & 15)) * SROW + (lane >> 4) * 16;
        const uint32_t bB = st + SUBT_A + (wn * 32 + (lane & 15)) * SROW + (lane >> 4) * 16;
        #pragma unroll
        for (int ks = 0; ks < 2; ks++) {
            const uint32_t ko = ks * 32;
            uint32_t a[4][4], bh[2][4];
            #pragma unroll
            for (int mi = 0; mi < 4; mi++) ldm_x4(a[mi], aB + mi * 16 * SROW + ko);
            #pragma unroll
            for (int nj = 0; nj < 2; nj++) ldm_x4(bh[nj], bB + nj * 16 * SROW + ko);
            #pragma unroll
            for (int mi = 0; mi < 4; mi++)
                #pragma unroll
                for (int n8 = 0; n8 < 4; n8++) {
                    const int nj = n8 >> 1, hl = n8 & 1;
                    mma16816(c[mi][n8], a[mi], bh[nj][hl], bh[nj][hl + 2]);
                }
        }
        if (kc + 2 < kSec) issue(kc + 2);
        else asm volatile("cp.async.commit_group;");
    }

    // epilogue
    const int r0b = mt * 128 + wm * 64 + (lane >> 2);
    const int ncb = nt * 64 + wn * 32 + (lane & 3) * 2;
    #pragma unroll
    for (int mi = 0; mi < 4; mi++) {
        #pragma unroll
        for (int n8 = 0; n8 < 4; n8++) {
            const int n = ncb + n8 * 8;
            const float b0 = bias[n], b1 = bias[n + 1];
            float* p0 = out + (size_t)(r0b + mi * 16) * AA + n;
            float* p1 = p0 + 8 * AA;
            float2 v0 = { c[mi][n8][0] + b0, c[mi][n8][1] + b1 };
            float2 v1 = { c[mi][n8][2] + b0, c[mi][n8][3] + b1 };
            *(float2*)p0 = v0;
            *(float2*)p1 = v1;
        }
    }
}

// ---------------------------------------------------------------------------
// K3a: scores. Block = (p-tile of 8 warps, b). att_enc row reused across 20 g.
// ---------------------------------------------------------------------------
__global__ __launch_bounds__(256) void k_score(
    const float* __restrict__ w_alpha, const float* __restrict__ b_alpha,
    float* __restrict__ score)
{
    __shared__ float sdec[GG * AA];   // 40KB
    __shared__ float sw_[AA];
    const int b = blockIdx.y;
    const int t = threadIdx.x, warp = t >> 5, lane = t & 31;

    const float* dptr = g_att_dec + (size_t)b * GG * AA;
    for (int i = t; i < GG * AA; i += 256) sdec[i] = dptr[i];
    for (int i = t; i < AA; i += 256) sw_[i] = w_alpha[i];
    __syncthreads();

    const int p = blockIdx.x * 8 + warp;
    if (p >= PP) return;
    const float ba = b_alpha[0];
    const float* ep = g_att_enc + ((size_t)b * PP + p) * AA;

    float e[16];
    #pragma unroll
    for (int i = 0; i < 16; i++) e[i] = ep[lane + 32 * i];

    for (int g = 0; g < GG; g++) {
        float s = 0.f;
        const float* dg = sdec + g * AA;
        #pragma unroll
        for (int i = 0; i < 16; i++) {
            int a = lane + 32 * i;
            float v = e[i] + dg[a];
            s = fmaf(fmaxf(v, 0.f), sw_[a], s);
        }
        #pragma unroll
        for (int o = 16; o > 0; o >>= 1)
            s += __shfl_xor_sync(0xffffffffu, s, o);
        if (lane == 0) score[((size_t)b * GG + g) * PP + p] = s + ba;
    }
}

// ---------------------------------------------------------------------------
// K3b: softmax over 196, writes alpha to output
// ---------------------------------------------------------------------------
__global__ __launch_bounds__(256) void k_softmax(
    const float* __restrict__ score, float* __restrict__ out_alpha)
{
    const int bg = blockIdx.x;
    __shared__ float ss[PP];
    __shared__ float red[8];
    const int t = threadIdx.x, warp = t >> 5, lane = t & 31;

    for (int p = t; p < PP; p += 256) ss[p] = score[(size_t)bg * PP + p];
    __syncthreads();

    float m = -1e30f;
    for (int p = t; p < PP; p += 256) m = fmaxf(m, ss[p]);
    #pragma unroll
    for (int o = 16; o > 0; o >>= 1) m = fmaxf(m, __shfl_xor_sync(0xffffffffu, m, o));
    if (lane == 0) red[warp] = m;
    __syncthreads();
    m = red[0];
    #pragma unroll
    for (int w = 1; w < 8; w++) m = fmaxf(m, red[w]);
    __syncthreads();

    float sum = 0.f;
    for (int p = t; p < PP; p += 256) {
        float ex = __expf(ss[p] - m);
        ss[p] = ex;
        sum += ex;
    }
    #pragma unroll
    for (int o = 16; o > 0; o >>= 1) sum += __shfl_xor_sync(0xffffffffu, sum, o);
    if (lane == 0) red[warp] = sum;
    __syncthreads();
    sum = 0.f;
    #pragma unroll
    for (int w = 0; w < 8; w++) sum += red[w];
    const float inv = 1.f / sum;
    __syncthreads();

    float* ao = out_alpha + (size_t)bg * PP;
    for (int p = t; p < PP; p += 256) ao[p] = ss[p] * inv;
}

// ---------------------------------------------------------------------------
// K3c: att_res[b,g,:] = sum_p alpha[b,g,p] * att_enc[b,p,:]
// ---------------------------------------------------------------------------
__global__ __launch_bounds__(256) void k_wsum(
    const float* __restrict__ alpha, float* __restrict__ out_res)
{
    __shared__ float sal[GG * PP];
    const int b = blockIdx.y, a0 = blockIdx.x * 128;
    const int t = threadIdx.x;
    const float* ap = alpha + (size_t)b * GG * PP;
    for (int i = t; i < GG * PP; i += 256) sal[i] = ap[i];
    __syncthreads();

    const int al = t & 127, h = t >> 7;
    float acc[10];
    #pragma unroll
    for (int j = 0; j < 10; j++) acc[j] = 0.f;

    const float* eb = g_att_enc + (size_t)b * PP * AA + a0 + al;
    for (int p = 0; p < PP; p++) {
        float v = eb[(size_t)p * AA];
        #pragma unroll
        for (int j = 0; j < 10; j++)
            acc[j] = fmaf(sal[(h * 10 + j) * PP + p], v, acc[j]);
    }
    #pragma unroll
    for (int j = 0; j < 10; j++)
        out_res[((size_t)b * GG + h * 10 + j) * AA + a0 + al] = acc[j];
}

// ---------------------------------------------------------------------------
extern "C" void kernel_launch(void* const* d_in, const int* in_sizes, int n_in,
                              void* d_out, int out_size)
{
    const float* enc     = (const float*)d_in[0];
    const float* dec     = (const float*)d_in[1];
    const float* W_enc   = (const float*)d_in[2];
    const float* b_enc   = (const float*)d_in[3];
    const float* W_dec   = (const float*)d_in[4];
    const float* b_dec   = (const float*)d_in[5];
    const float* w_alpha = (const float*)d_in[6];
    const float* b_alpha = (const float*)d_in[7];

    float* out = (float*)d_out;
    float* out_res   = out;                        // (B,G,A)
    float* out_alpha = out + (size_t)M2 * AA;      // (B,G,P)

    __half *A1, *B1, *A2, *B2;
    float *att_enc, *att_dec, *score;
    cudaGetSymbolAddress((void**)&A1, g_A1);
    cudaGetSymbolAddress((void**)&B1, g_B1);
    cudaGetSymbolAddress((void**)&A2, g_A2);
    cudaGetSymbolAddress((void**)&B2, g_B2);
    cudaGetSymbolAddress((void**)&att_enc, g_att_enc);
    cudaGetSymbolAddress((void**)&att_dec, g_att_dec);
    cudaGetSymbolAddress((void**)&score, g_score);

    cudaFuncSetAttribute(k_mma16, cudaFuncAttributeMaxDynamicSharedMemorySize, SMEM_GEMM);

    // prep
    k_prep_A_enc<<<dim3(KSEC1, MT1), 256>>>(enc, A1);
    k_prep_B    <<<dim3(KSEC1, 4),   256>>>(W_enc, B1, KSEC1);
    k_prep_A_dec<<<dim3(KSEC2, MT2), 256>>>(dec, A2);
    k_prep_B    <<<dim3(KSEC2, 4),   256>>>(W_dec, B2, KSEC2);

    // GEMMs (single-product fp16)
    k_mma16<<<dim3(8, MT1), 128, SMEM_GEMM>>>(A1, B1, b_enc, att_enc, KSEC1);
    k_mma16<<<dim3(8, MT2), 128, SMEM_GEMM>>>(A2, B2, b_dec, att_dec, KSEC2);

    // attention tail
    k_score  <<<dim3(25, BATCH), 256>>>(w_alpha, b_alpha, score);
    k_softmax<<<M2, 256>>>(score, out_alpha);
    k_wsum   <<<dim3(4, BATCH), 256>>>(out_alpha, out_res);
}

// round 6
// speedup vs baseline: 3.6859x; 1.0132x over previous
#include <cuda_runtime.h>
#include <cuda_fp16.h>
#include <cstdint>

// Problem constants
#define BATCH 32
#define CC 2048       // channels (K of GEMM1)
#define PP 196        // H*W
#define GG 20         // decoder steps
#define DD 1024       // decode size (K of GEMM2)
#define AA 512        // att size (N of both GEMMs)

#define M1 (BATCH*PP)      // 6272 = 49*128
#define MT1 49
#define M2 (BATCH*GG)      // 640 = 5*128
#define MT2 5
#define KSEC1 64           // 2048/32 k-chunks (GEMM1)
#define KSEC2 32           // 1024/32 (GEMM2)

// GEMM tiling: CTA 128x64, 4 warps (2x2), warp 64x32, chunk K=32.
#define STAGES 3
#define CHUNK_A 8192              // 128 x 32 x 2B
#define CHUNK_B 4096              // 64 x 32 x 2B
#define SROW 80                   // smem row pitch (64B data + 16B pad)
#define SUBT_A (128*SROW)         // 10240
#define SUBT_B (64*SROW)          // 5120
#define STAGE_BYTES (SUBT_A + SUBT_B)    // 15360
#define SMEM_GEMM (STAGES*STAGE_BYTES)   // 46080

// ---------------------------------------------------------------------------
// Scratch
// ---------------------------------------------------------------------------
__device__ __align__(16) __half g_A1[MT1 * KSEC1 * 4096];   // 25.7 MB
__device__ __align__(16) __half g_B1[8   * KSEC1 * 2048];   // 2.1 MB
__device__ __align__(16) __half g_A2[MT2 * KSEC2 * 4096];
__device__ __align__(16) __half g_B2[8   * KSEC2 * 2048];
__device__ __align__(16) __half g_att_encH[M1*AA];   // (B,P,A) fp16, 6.4MB
__device__ float g_att_dec[M2*AA];                   // (B,G,A) fp32
__device__ float g_score[M2*PP];                     // (B,G,P)

// ---------------------------------------------------------------------------
__device__ __forceinline__ uint32_t smem_u32(const void* p) {
    uint32_t a;
    asm("{ .reg .u64 t; cvta.to.shared.u64 t, %1; cvt.u32.u64 %0, t; }" : "=r"(a) : "l"(p));
    return a;
}
__device__ __forceinline__ void cp16(uint32_t saddr, const void* gaddr) {
    asm volatile("cp.async.cg.shared.global [%0], [%1], 16;" :: "r"(saddr), "l"(gaddr));
}
__device__ __forceinline__ void ldm_x4(uint32_t* r, uint32_t addr) {
    asm volatile("ldmatrix.sync.aligned.m8n8.x4.shared.b16 {%0,%1,%2,%3}, [%4];"
        : "=r"(r[0]), "=r"(r[1]), "=r"(r[2]), "=r"(r[3]) : "r"(addr));
}
__device__ __forceinline__ void mma16816(float* c, const uint32_t* a, uint32_t b0, uint32_t b1) {
    asm volatile("mma.sync.aligned.m16n8k16.row.col.f32.f16.f16.f32 "
        "{%0,%1,%2,%3}, {%4,%5,%6,%7}, {%8,%9}, {%0,%1,%2,%3};"
        : "+f"(c[0]), "+f"(c[1]), "+f"(c[2]), "+f"(c[3])
        : "r"(a[0]), "r"(a[1]), "r"(a[2]), "r"(a[3]), "r"(b0), "r"(b1));
}

// ---------------------------------------------------------------------------
// Prep: enc (B,C,P) transpose -> A1 chunks. grid (KSEC1, MT1)
// ---------------------------------------------------------------------------
__global__ __launch_bounds__(256) void k_prep_A_enc(
    const float* __restrict__ enc, __half* __restrict__ Ast)
{
    __shared__ float sm[32 * 129];
    const int kc = blockIdx.x, mt = blockIdx.y;
    const int t = threadIdx.x;
    #pragma unroll
    for (int i = 0; i < 16; i++) {
        int idx = t + i * 256;            // 4096 = 32c x 128m
        int cl = idx >> 7, ml = idx & 127;
        int m = mt * 128 + ml;
        int b = m / PP, p = m - b * PP;
        sm[cl * 129 + ml] = enc[((size_t)b * CC + (kc * 32 + cl)) * PP + p];
    }
    __syncthreads();
    __half2* hiC = (__half2*)(Ast + ((size_t)mt * KSEC1 + kc) * 4096);
    #pragma unroll
    for (int i = 0; i < 8; i++) {
        int e2 = t + i * 256;             // 2048 half2 = 128r x 16
        int row = e2 >> 4, cp = e2 & 15;
        float x0 = sm[(2*cp)   * 129 + row];
        float x1 = sm[(2*cp+1) * 129 + row];
        hiC[row * 16 + cp] = __halves2half2(__float2half_rn(x0), __float2half_rn(x1));
    }
}

// B-prep body: W (K,512) -> 64-row n-tiles, transposed chunks
__device__ __forceinline__ void prep_B_body(
    const float* __restrict__ W, __half* __restrict__ Bst, int kSec,
    int kc, int nb, int t, float* sm)
{
    #pragma unroll
    for (int i = 0; i < 16; i++) {
        int idx = t + i * 256;
        int kl = idx >> 7, nl = idx & 127;
        sm[kl * 129 + nl] = W[(size_t)(kc * 32 + kl) * AA + nb * 128 + nl];
    }
    __syncthreads();
    #pragma unroll
    for (int i = 0; i < 8; i++) {
        int e2 = t + i * 256;
        int row = e2 >> 4, cp = e2 & 15;
        float x0 = sm[(2*cp)   * 129 + row];
        float x1 = sm[(2*cp+1) * 129 + row];
        int nt = nb * 2 + (row >> 6);
        int rl = row & 63;
        __half2* dst = (__half2*)(Bst + ((size_t)nt * kSec + kc) * 2048);
        dst[rl * 16 + cp] = __halves2half2(__float2half_rn(x0), __float2half_rn(x1));
    }
}

// Merged small-prep kernel: W_enc (256 blk) | W_dec (128 blk) | dec (160 blk)
__global__ __launch_bounds__(256) void k_prep_misc(
    const float* __restrict__ W_enc, const float* __restrict__ W_dec,
    const float* __restrict__ dec,
    __half* __restrict__ B1, __half* __restrict__ B2, __half* __restrict__ A2)
{
    __shared__ float sm[32 * 129];
    const int id = blockIdx.x;
    const int t = threadIdx.x;
    if (id < 256) {
        prep_B_body(W_enc, B1, KSEC1, id & 63, id >> 6, t, sm);
    } else if (id < 384) {
        int j = id - 256;
        prep_B_body(W_dec, B2, KSEC2, j & 31, j >> 5, t, sm);
    } else {
        int j = id - 384;
        int kc = j & 31, mt = j >> 5;
        __half2* hiC = (__half2*)(A2 + ((size_t)mt * KSEC2 + kc) * 4096);
        #pragma unroll
        for (int i = 0; i < 8; i++) {
            int e2 = t + i * 256;
            int row = e2 >> 4, cp = e2 & 15;
            const float* src = dec + (size_t)(mt * 128 + row) * DD + kc * 32 + 2*cp;
            hiC[row * 16 + cp] = __halves2half2(__float2half_rn(src[0]), __float2half_rn(src[1]));
        }
    }
}

// ---------------------------------------------------------------------------
// fp16 mma.sync GEMM (single product). CTA 128x64, 128 threads, 3 stages.
// OUTH: write fp16 half2 output (att_enc); else fp32.
// ---------------------------------------------------------------------------
template<bool OUTH>
__global__ __launch_bounds__(128, 3) void k_mma16(
    const __half* __restrict__ Ast, const __half* __restrict__ Bst,
    const float* __restrict__ bias, void* __restrict__ outv, int kSec)
{
    extern __shared__ __align__(16) char smem[];
    const int t = threadIdx.x;
    const int lane = t & 31, wid = t >> 5;
    const int wm = wid >> 1, wn = wid & 1;        // warp tile (wm*64, wn*32)
    const int mt = blockIdx.y, nt = blockIdx.x;

    const char* Abase = (const char*)(Ast + (size_t)mt * kSec * 4096);
    const char* Bbase = (const char*)(Bst + (size_t)nt * kSec * 2048);
    const uint32_t smem_base = smem_u32(smem);

    auto issue = [&](int kc) {
        const int s = kc % STAGES;
        const char* ga = Abase + (size_t)kc * CHUNK_A;
        const char* gb = Bbase + (size_t)kc * CHUNK_B;
        const uint32_t st = smem_base + s * STAGE_BYTES;
        #pragma unroll
        for (int j = 0; j < 4; j++) {     // A: 512 16B-chunks
            int u = t + j * 128;
            cp16(st + (u >> 2) * SROW + (u & 3) * 16, ga + u * 16);
        }
        #pragma unroll
        for (int j = 0; j < 2; j++) {     // B: 256 16B-chunks
            int u = t + j * 128;
            cp16(st + SUBT_A + (u >> 2) * SROW + (u & 3) * 16, gb + u * 16);
        }
        asm volatile("cp.async.commit_group;");
    };

    issue(0); issue(1);

    float c[4][4][4];
    #pragma unroll
    for (int mi = 0; mi < 4; mi++)
        #pragma unroll
        for (int nj = 0; nj < 4; nj++)
            #pragma unroll
            for (int q = 0; q < 4; q++) c[mi][nj][q] = 0.f;

    for (int kc = 0; kc < kSec; kc++) {
        asm volatile("cp.async.wait_group 1;");
        __syncthreads();
        const int s = kc % STAGES;
        const uint32_t st = smem_base + s * STAGE_BYTES;
        const uint32_t aB = st + (wm * 64 + (lane & 15)) * SROW + (lane >> 4) * 16;
        const uint32_t bB = st + SUBT_A + (wn * 32 + (lane & 15)) * SROW + (lane >> 4) * 16;
        #pragma unroll
        for (int ks = 0; ks < 2; ks++) {
            const uint32_t ko = ks * 32;
            uint32_t a[4][4], bh[2][4];
            #pragma unroll
            for (int mi = 0; mi < 4; mi++) ldm_x4(a[mi], aB + mi * 16 * SROW + ko);
            #pragma unroll
            for (int nj = 0; nj < 2; nj++) ldm_x4(bh[nj], bB + nj * 16 * SROW + ko);
            #pragma unroll
            for (int mi = 0; mi < 4; mi++)
                #pragma unroll
                for (int n8 = 0; n8 < 4; n8++) {
                    const int nj = n8 >> 1, hl = n8 & 1;
                    mma16816(c[mi][n8], a[mi], bh[nj][hl], bh[nj][hl + 2]);
                }
        }
        if (kc + 2 < kSec) issue(kc + 2);
        else asm volatile("cp.async.commit_group;");
    }

    // epilogue
    const int r0b = mt * 128 + wm * 64 + (lane >> 2);
    const int ncb = nt * 64 + wn * 32 + (lane & 3) * 2;
    #pragma unroll
    for (int mi = 0; mi < 4; mi++) {
        #pragma unroll
        for (int n8 = 0; n8 < 4; n8++) {
            const int n = ncb + n8 * 8;
            const float b0 = bias[n], b1 = bias[n + 1];
            const size_t o0 = (size_t)(r0b + mi * 16) * AA + n;
            if (OUTH) {
                __half* out = (__half*)outv;
                *(__half2*)(out + o0) =
                    __floats2half2_rn(c[mi][n8][0] + b0, c[mi][n8][1] + b1);
                *(__half2*)(out + o0 + 8 * AA) =
                    __floats2half2_rn(c[mi][n8][2] + b0, c[mi][n8][3] + b1);
            } else {
                float* out = (float*)outv;
                float2 v0 = { c[mi][n8][0] + b0, c[mi][n8][1] + b1 };
                float2 v1 = { c[mi][n8][2] + b0, c[mi][n8][3] + b1 };
                *(float2*)(out + o0) = v0;
                *(float2*)(out + o0 + 8 * AA) = v1;
            }
        }
    }
}

// ---------------------------------------------------------------------------
// K3a: scores. Block = (p-tile of 8 warps, b). att_enc fp16, reused over 20 g.
// ---------------------------------------------------------------------------
__global__ __launch_bounds__(256) void k_score(
    const float* __restrict__ w_alpha, const float* __restrict__ b_alpha,
    float* __restrict__ score)
{
    __shared__ float sdec[GG * AA];   // 40KB
    __shared__ float sw_[AA];
    const int b = blockIdx.y;
    const int t = threadIdx.x, warp = t >> 5, lane = t & 31;

    const float* dptr = g_att_dec + (size_t)b * GG * AA;
    for (int i = t; i < GG * AA; i += 256) sdec[i] = dptr[i];
    for (int i = t; i < AA; i += 256) sw_[i] = w_alpha[i];
    __syncthreads();

    const int p = blockIdx.x * 8 + warp;
    if (p >= PP) return;
    const float ba = b_alpha[0];
    const __half2* ep = (const __half2*)(g_att_encH + ((size_t)b * PP + p) * AA);

    float2 e[8];
    #pragma unroll
    for (int i = 0; i < 8; i++) e[i] = __half22float2(ep[lane + 32 * i]);

    for (int g = 0; g < GG; g++) {
        float s = 0.f;
        const float* dg = sdec + g * AA;
        #pragma unroll
        for (int i = 0; i < 8; i++) {
            int a = 2 * (lane + 32 * i);
            float2 d2 = *(const float2*)&dg[a];
            float2 w2 = *(const float2*)&sw_[a];
            s = fmaf(fmaxf(e[i].x + d2.x, 0.f), w2.x, s);
            s = fmaf(fmaxf(e[i].y + d2.y, 0.f), w2.y, s);
        }
        #pragma unroll
        for (int o = 16; o > 0; o >>= 1)
            s += __shfl_xor_sync(0xffffffffu, s, o);
        if (lane == 0) score[((size_t)b * GG + g) * PP + p] = s + ba;
    }
}

// ---------------------------------------------------------------------------
// K3b (fused): softmax over p (warp per g, in smem) + weighted sum.
// grid (4 a-chunks, B); chunk 0 also writes alpha.
// ---------------------------------------------------------------------------
__global__ __launch_bounds__(256) void k_soft_wsum(
    const float* __restrict__ score, float* __restrict__ out_alpha,
    float* __restrict__ out_res)
{
    __shared__ float sal[GG * PP];   // 15.7KB
    const int b = blockIdx.y, a0 = blockIdx.x * 128;
    const int t = threadIdx.x, warp = t >> 5, lane = t & 31;

    const float* sp = score + (size_t)b * GG * PP;
    for (int i = t; i < GG * PP; i += 256) sal[i] = sp[i];
    __syncthreads();

    // softmax: warp per g (20 rows, 8 warps)
    for (int g = warp; g < GG; g += 8) {
        float* row = sal + g * PP;
        float m = -1e30f;
        for (int p = lane; p < PP; p += 32) m = fmaxf(m, row[p]);
        #pragma unroll
        for (int o = 16; o > 0; o >>= 1)
            m = fmaxf(m, __shfl_xor_sync(0xffffffffu, m, o));
        float sum = 0.f;
        for (int p = lane; p < PP; p += 32) {
            float ex = __expf(row[p] - m);
            row[p] = ex;
            sum += ex;
        }
        #pragma unroll
        for (int o = 16; o > 0; o >>= 1)
            sum += __shfl_xor_sync(0xffffffffu, sum, o);
        const float inv = 1.f / sum;
        for (int p = lane; p < PP; p += 32) row[p] *= inv;
    }
    __syncthreads();

    if (blockIdx.x == 0) {
        float* ao = out_alpha + (size_t)b * GG * PP;
        for (int i = t; i < GG * PP; i += 256) ao[i] = sal[i];
    }

    // weighted sum: thread = (a_local 0..127, g-half); 10 accumulators
    const int al = t & 127, h = t >> 7;
    float acc[10];
    #pragma unroll
    for (int j = 0; j < 10; j++) acc[j] = 0.f;

    const __half* eb = g_att_encH + (size_t)b * PP * AA + a0 + al;
    for (int p = 0; p < PP; p++) {
        float v = __half2float(eb[(size_t)p * AA]);
        #pragma unroll
        for (int j = 0; j < 10; j++)
            acc[j] = fmaf(sal[(h * 10 + j) * PP + p], v, acc[j]);
    }
    #pragma unroll
    for (int j = 0; j < 10; j++)
        out_res[((size_t)b * GG + h * 10 + j) * AA + a0 + al] = acc[j];
}

// ---------------------------------------------------------------------------
extern "C" void kernel_launch(void* const* d_in, const int* in_sizes, int n_in,
                              void* d_out, int out_size)
{
    const float* enc     = (const float*)d_in[0];
    const float* dec     = (const float*)d_in[1];
    const float* W_enc   = (const float*)d_in[2];
    const float* b_enc   = (const float*)d_in[3];
    const float* W_dec   = (const float*)d_in[4];
    const float* b_dec   = (const float*)d_in[5];
    const float* w_alpha = (const float*)d_in[6];
    const float* b_alpha = (const float*)d_in[7];

    float* out = (float*)d_out;
    float* out_res   = out;                        // (B,G,A)
    float* out_alpha = out + (size_t)M2 * AA;      // (B,G,P)

    __half *A1, *B1, *A2, *B2, *attH;
    float *att_dec, *score;
    cudaGetSymbolAddress((void**)&A1, g_A1);
    cudaGetSymbolAddress((void**)&B1, g_B1);
    cudaGetSymbolAddress((void**)&A2, g_A2);
    cudaGetSymbolAddress((void**)&B2, g_B2);
    cudaGetSymbolAddress((void**)&attH, g_att_encH);
    cudaGetSymbolAddress((void**)&att_dec, g_att_dec);
    cudaGetSymbolAddress((void**)&score, g_score);

    cudaFuncSetAttribute(k_mma16<true>,  cudaFuncAttributeMaxDynamicSharedMemorySize, SMEM_GEMM);
    cudaFuncSetAttribute(k_mma16<false>, cudaFuncAttributeMaxDynamicSharedMemorySize, SMEM_GEMM);

    // prep
    k_prep_A_enc<<<dim3(KSEC1, MT1), 256>>>(enc, A1);
    k_prep_misc <<<544, 256>>>(W_enc, W_dec, dec, B1, B2, A2);

    // GEMMs (single-product fp16)
    k_mma16<true> <<<dim3(8, MT1), 128, SMEM_GEMM>>>(A1, B1, b_enc, attH, KSEC1);
    k_mma16<false><<<dim3(8, MT2), 128, SMEM_GEMM>>>(A2, B2, b_dec, att_dec, KSEC2);

    // attention tail
    k_score    <<<dim3(25, BATCH), 256>>>(w_alpha, b_alpha, score);
    k_soft_wsum<<<dim3(4, BATCH), 256>>>(score, out_alpha, out_res);
}

// round 7
// speedup vs baseline: 4.3706x; 1.1858x over previous
#include <cuda_runtime.h>
#include <cuda_fp16.h>
#include <cstdint>

// Problem constants
#define BATCH 32
#define CC 2048       // channels (K of GEMM1)
#define PP 196        // H*W
#define GG 20         // decoder steps
#define DD 1024       // decode size (K of GEMM2)
#define AA 512        // att size (N of both GEMMs)

#define M1 (BATCH*PP)      // 6272 = 49*128
#define MT1 49
#define M2 (BATCH*GG)      // 640 = 5*128
#define MT2 5
#define KSEC1 64           // 2048/32 k-chunks (GEMM1)
#define KSEC2 32           // 1024/32 (GEMM2)

// GEMM tiling: CTA 128x64, 4 warps (2x2), warp 64x32, chunk K=32.
#define STAGES 3
#define CHUNK_A 8192              // 128 x 32 x 2B
#define CHUNK_B 4096              // 64 x 32 x 2B
#define SROW 80                   // smem row pitch (64B data + 16B pad)
#define SUBT_A (128*SROW)         // 10240
#define SUBT_B (64*SROW)          // 5120
#define STAGE_BYTES (SUBT_A + SUBT_B)    // 15360
#define SMEM_GEMM (STAGES*STAGE_BYTES)   // 46080

#define G1_BLOCKS (8*MT1)         // 392
#define G2_BLOCKS (8*MT2)         // 40

// ---------------------------------------------------------------------------
// Scratch
// ---------------------------------------------------------------------------
__device__ __align__(16) __half g_A1[MT1 * KSEC1 * 4096];   // 25.7 MB
__device__ __align__(16) __half g_B1[8   * KSEC1 * 2048];   // 2.1 MB
__device__ __align__(16) __half g_A2[MT2 * KSEC2 * 4096];
__device__ __align__(16) __half g_B2[8   * KSEC2 * 2048];
__device__ __align__(16) __half g_att_encH[M1*AA];   // (B,P,A) fp16, 6.4MB
__device__ float g_att_dec[M2*AA];                   // (B,G,A) fp32
__device__ float g_score[M2*PP];                     // (B,G,P)

// ---------------------------------------------------------------------------
__device__ __forceinline__ uint32_t smem_u32(const void* p) {
    uint32_t a;
    asm("{ .reg .u64 t; cvta.to.shared.u64 t, %1; cvt.u32.u64 %0, t; }" : "=r"(a) : "l"(p));
    return a;
}
__device__ __forceinline__ void cp16(uint32_t saddr, const void* gaddr) {
    asm volatile("cp.async.cg.shared.global [%0], [%1], 16;" :: "r"(saddr), "l"(gaddr));
}
__device__ __forceinline__ void ldm_x4(uint32_t* r, uint32_t addr) {
    asm volatile("ldmatrix.sync.aligned.m8n8.x4.shared.b16 {%0,%1,%2,%3}, [%4];"
        : "=r"(r[0]), "=r"(r[1]), "=r"(r[2]), "=r"(r[3]) : "r"(addr));
}
__device__ __forceinline__ void mma16816(float* c, const uint32_t* a, uint32_t b0, uint32_t b1) {
    asm volatile("mma.sync.aligned.m16n8k16.row.col.f32.f16.f16.f32 "
        "{%0,%1,%2,%3}, {%4,%5,%6,%7}, {%8,%9}, {%0,%1,%2,%3};"
        : "+f"(c[0]), "+f"(c[1]), "+f"(c[2]), "+f"(c[3])
        : "r"(a[0]), "r"(a[1]), "r"(a[2]), "r"(a[3]), "r"(b0), "r"(b1));
}

// ---------------------------------------------------------------------------
// Merged prep kernel.
// id < 3136          : A_enc transpose chunks   (kc = id & 63, mt = id >> 6)
// 3136 <= id < 3392  : B1 (W_enc)               (256 blocks)
// 3392 <= id < 3520  : B2 (W_dec)               (128 blocks)
// 3520 <= id < 3680  : A2 (dec)                 (160 blocks)
// ---------------------------------------------------------------------------
__device__ __forceinline__ void prep_B_body(
    const float* __restrict__ W, __half* __restrict__ Bst, int kSec,
    int kc, int nb, int t, float* sm)
{
    #pragma unroll
    for (int i = 0; i < 16; i++) {
        int idx = t + i * 256;
        int kl = idx >> 7, nl = idx & 127;
        sm[kl * 129 + nl] = W[(size_t)(kc * 32 + kl) * AA + nb * 128 + nl];
    }
    __syncthreads();
    #pragma unroll
    for (int i = 0; i < 8; i++) {
        int e2 = t + i * 256;
        int row = e2 >> 4, cp = e2 & 15;
        float x0 = sm[(2*cp)   * 129 + row];
        float x1 = sm[(2*cp+1) * 129 + row];
        int nt = nb * 2 + (row >> 6);
        int rl = row & 63;
        __half2* dst = (__half2*)(Bst + ((size_t)nt * kSec + kc) * 2048);
        dst[rl * 16 + cp] = __halves2half2(__float2half_rn(x0), __float2half_rn(x1));
    }
}

__global__ __launch_bounds__(256) void k_prep_all(
    const float* __restrict__ enc, const float* __restrict__ dec,
    const float* __restrict__ W_enc, const float* __restrict__ W_dec,
    __half* __restrict__ A1, __half* __restrict__ B1,
    __half* __restrict__ A2, __half* __restrict__ B2)
{
    __shared__ float sm[32 * 129];
    const int id = blockIdx.x;
    const int t = threadIdx.x;

    if (id < 3136) {
        const int kc = id & 63, mt = id >> 6;
        #pragma unroll
        for (int i = 0; i < 16; i++) {
            int idx = t + i * 256;            // 4096 = 32c x 128m
            int cl = idx >> 7, ml = idx & 127;
            int m = mt * 128 + ml;
            int b = m / PP, p = m - b * PP;
            sm[cl * 129 + ml] = enc[((size_t)b * CC + (kc * 32 + cl)) * PP + p];
        }
        __syncthreads();
        __half2* hiC = (__half2*)(A1 + ((size_t)mt * KSEC1 + kc) * 4096);
        #pragma unroll
        for (int i = 0; i < 8; i++) {
            int e2 = t + i * 256;             // 2048 half2 = 128r x 16
            int row = e2 >> 4, cp = e2 & 15;
            float x0 = sm[(2*cp)   * 129 + row];
            float x1 = sm[(2*cp+1) * 129 + row];
            hiC[row * 16 + cp] = __halves2half2(__float2half_rn(x0), __float2half_rn(x1));
        }
    } else if (id < 3392) {
        int j = id - 3136;
        prep_B_body(W_enc, B1, KSEC1, j & 63, j >> 6, t, sm);
    } else if (id < 3520) {
        int j = id - 3392;
        prep_B_body(W_dec, B2, KSEC2, j & 31, j >> 5, t, sm);
    } else {
        int j = id - 3520;
        int kc = j & 31, mt = j >> 5;
        __half2* hiC = (__half2*)(A2 + ((size_t)mt * KSEC2 + kc) * 4096);
        #pragma unroll
        for (int i = 0; i < 8; i++) {
            int e2 = t + i * 256;
            int row = e2 >> 4, cp = e2 & 15;
            const float* src = dec + (size_t)(mt * 128 + row) * DD + kc * 32 + 2*cp;
            hiC[row * 16 + cp] = __halves2half2(__float2half_rn(src[0]), __float2half_rn(src[1]));
        }
    }
}

// ---------------------------------------------------------------------------
// Merged fp16 mma.sync GEMM (single product). CTA 128x64, 128 threads, 3 stages.
// id < 392: GEMM1 (A1 x B1 -> att_encH fp16).  id >= 392: GEMM2 (-> att_dec fp32)
// ---------------------------------------------------------------------------
__global__ __launch_bounds__(128, 3) void k_gemm_all(
    const __half* __restrict__ A1g, const __half* __restrict__ B1g,
    const __half* __restrict__ A2g, const __half* __restrict__ B2g,
    const float* __restrict__ b_enc, const float* __restrict__ b_dec,
    __half* __restrict__ out1, float* __restrict__ out2)
{
    extern __shared__ __align__(16) char smem[];
    const int id = blockIdx.x;
    const int t = threadIdx.x;
    const int lane = t & 31, wid = t >> 5;
    const int wm = wid >> 1, wn = wid & 1;        // warp tile (wm*64, wn*32)

    const bool g1 = (id < G1_BLOCKS);
    const int j  = g1 ? id : id - G1_BLOCKS;
    const int mt = j >> 3, nt = j & 7;
    const int kSec = g1 ? KSEC1 : KSEC2;
    const __half* Ast = g1 ? A1g : A2g;
    const __half* Bst = g1 ? B1g : B2g;
    const float* bias = g1 ? b_enc : b_dec;

    const char* Abase = (const char*)(Ast + (size_t)mt * kSec * 4096);
    const char* Bbase = (const char*)(Bst + (size_t)nt * kSec * 2048);
    const uint32_t smem_base = smem_u32(smem);

    auto issue = [&](int kc) {
        const int s = kc % STAGES;
        const char* ga = Abase + (size_t)kc * CHUNK_A;
        const char* gb = Bbase + (size_t)kc * CHUNK_B;
        const uint32_t st = smem_base + s * STAGE_BYTES;
        #pragma unroll
        for (int jj = 0; jj < 4; jj++) {   // A: 512 16B-chunks
            int u = t + jj * 128;
            cp16(st + (u >> 2) * SROW + (u & 3) * 16, ga + u * 16);
        }
        #pragma unroll
        for (int jj = 0; jj < 2; jj++) {   // B: 256 16B-chunks
            int u = t + jj * 128;
            cp16(st + SUBT_A + (u >> 2) * SROW + (u & 3) * 16, gb + u * 16);
        }
        asm volatile("cp.async.commit_group;");
    };

    issue(0); issue(1);

    float c[4][4][4];
    #pragma unroll
    for (int mi = 0; mi < 4; mi++)
        #pragma unroll
        for (int nj = 0; nj < 4; nj++)
            #pragma unroll
            for (int q = 0; q < 4; q++) c[mi][nj][q] = 0.f;

    for (int kc = 0; kc < kSec; kc++) {
        asm volatile("cp.async.wait_group 1;");
        __syncthreads();
        const int s = kc % STAGES;
        const uint32_t st = smem_base + s * STAGE_BYTES;
        const uint32_t aB = st + (wm * 64 + (lane & 15)) * SROW + (lane >> 4) * 16;
        const uint32_t bB = st + SUBT_A + (wn * 32 + (lane & 15)) * SROW + (lane >> 4) * 16;
        #pragma unroll
        for (int ks = 0; ks < 2; ks++) {
            const uint32_t ko = ks * 32;
            uint32_t a[4][4], bh[2][4];
            #pragma unroll
            for (int mi = 0; mi < 4; mi++) ldm_x4(a[mi], aB + mi * 16 * SROW + ko);
            #pragma unroll
            for (int nj = 0; nj < 2; nj++) ldm_x4(bh[nj], bB + nj * 16 * SROW + ko);
            #pragma unroll
            for (int mi = 0; mi < 4; mi++)
                #pragma unroll
                for (int n8 = 0; n8 < 4; n8++) {
                    const int nj = n8 >> 1, hl = n8 & 1;
                    mma16816(c[mi][n8], a[mi], bh[nj][hl], bh[nj][hl + 2]);
                }
        }
        if (kc + 2 < kSec) issue(kc + 2);
        else asm volatile("cp.async.commit_group;");
    }

    // epilogue
    const int r0b = mt * 128 + wm * 64 + (lane >> 2);
    const int ncb = nt * 64 + wn * 32 + (lane & 3) * 2;
    #pragma unroll
    for (int mi = 0; mi < 4; mi++) {
        #pragma unroll
        for (int n8 = 0; n8 < 4; n8++) {
            const int n = ncb + n8 * 8;
            const float b0 = bias[n], b1 = bias[n + 1];
            const size_t o0 = (size_t)(r0b + mi * 16) * AA + n;
            if (g1) {
                *(__half2*)(out1 + o0) =
                    __floats2half2_rn(c[mi][n8][0] + b0, c[mi][n8][1] + b1);
                *(__half2*)(out1 + o0 + 8 * AA) =
                    __floats2half2_rn(c[mi][n8][2] + b0, c[mi][n8][3] + b1);
            } else {
                float2 v0 = { c[mi][n8][0] + b0, c[mi][n8][1] + b1 };
                float2 v1 = { c[mi][n8][2] + b0, c[mi][n8][3] + b1 };
                *(float2*)(out2 + o0) = v0;
                *(float2*)(out2 + o0 + 8 * AA) = v1;
            }
        }
    }
}

// ---------------------------------------------------------------------------
// K3a: scores. Block = (p-tile of 8 warps, b). att_enc fp16, reused over 20 g.
// ---------------------------------------------------------------------------
__global__ __launch_bounds__(256) void k_score(
    const float* __restrict__ w_alpha, const float* __restrict__ b_alpha,
    float* __restrict__ score)
{
    __shared__ float sdec[GG * AA];   // 40KB
    __shared__ float sw_[AA];
    const int b = blockIdx.y;
    const int t = threadIdx.x, warp = t >> 5, lane = t & 31;

    const float* dptr = g_att_dec + (size_t)b * GG * AA;
    for (int i = t; i < GG * AA; i += 256) sdec[i] = dptr[i];
    for (int i = t; i < AA; i += 256) sw_[i] = w_alpha[i];
    __syncthreads();

    const int p = blockIdx.x * 8 + warp;
    if (p >= PP) return;
    const float ba = b_alpha[0];
    const __half2* ep = (const __half2*)(g_att_encH + ((size_t)b * PP + p) * AA);

    float2 e[8];
    #pragma unroll
    for (int i = 0; i < 8; i++) e[i] = __half22float2(ep[lane + 32 * i]);

    for (int g = 0; g < GG; g++) {
        float s = 0.f;
        const float* dg = sdec + g * AA;
        #pragma unroll
        for (int i = 0; i < 8; i++) {
            int a = 2 * (lane + 32 * i);
            float2 d2 = *(const float2*)&dg[a];
            float2 w2 = *(const float2*)&sw_[a];
            s = fmaf(fmaxf(e[i].x + d2.x, 0.f), w2.x, s);
            s = fmaf(fmaxf(e[i].y + d2.y, 0.f), w2.y, s);
        }
        #pragma unroll
        for (int o = 16; o > 0; o >>= 1)
            s += __shfl_xor_sync(0xffffffffu, s, o);
        if (lane == 0) score[((size_t)b * GG + g) * PP + p] = s + ba;
    }
}

// ---------------------------------------------------------------------------
// K3b (fused): softmax over p (warp per g, in smem) + weighted sum.
// grid (4 a-chunks, B); chunk 0 also writes alpha.
// ---------------------------------------------------------------------------
__global__ __launch_bounds__(256) void k_soft_wsum(
    const float* __restrict__ score, float* __restrict__ out_alpha,
    float* __restrict__ out_res)
{
    __shared__ float sal[GG * PP];   // 15.7KB
    const int b = blockIdx.y, a0 = blockIdx.x * 128;
    const int t = threadIdx.x, warp = t >> 5, lane = t & 31;

    const float* sp = score + (size_t)b * GG * PP;
    for (int i = t; i < GG * PP; i += 256) sal[i] = sp[i];
    __syncthreads();

    // softmax: warp per g (20 rows, 8 warps)
    for (int g = warp; g < GG; g += 8) {
        float* row = sal + g * PP;
        float m = -1e30f;
        for (int p = lane; p < PP; p += 32) m = fmaxf(m, row[p]);
        #pragma unroll
        for (int o = 16; o > 0; o >>= 1)
            m = fmaxf(m, __shfl_xor_sync(0xffffffffu, m, o));
        float sum = 0.f;
        for (int p = lane; p < PP; p += 32) {
            float ex = __expf(row[p] - m);
            row[p] = ex;
            sum += ex;
        }
        #pragma unroll
        for (int o = 16; o > 0; o >>= 1)
            sum += __shfl_xor_sync(0xffffffffu, sum, o);
        const float inv = 1.f / sum;
        for (int p = lane; p < PP; p += 32) row[p] *= inv;
    }
    __syncthreads();

    if (blockIdx.x == 0) {
        float* ao = out_alpha + (size_t)b * GG * PP;
        for (int i = t; i < GG * PP; i += 256) ao[i] = sal[i];
    }

    // weighted sum: thread = (a_local 0..127, g-half); 10 accumulators
    const int al = t & 127, h = t >> 7;
    float acc[10];
    #pragma unroll
    for (int j = 0; j < 10; j++) acc[j] = 0.f;

    const __half* eb = g_att_encH + (size_t)b * PP * AA + a0 + al;
    for (int p = 0; p < PP; p++) {
        float v = __half2float(eb[(size_t)p * AA]);
        #pragma unroll
        for (int j = 0; j < 10; j++)
            acc[j] = fmaf(sal[(h * 10 + j) * PP + p], v, acc[j]);
    }
    #pragma unroll
    for (int j = 0; j < 10; j++)
        out_res[((size_t)b * GG + h * 10 + j) * AA + a0 + al] = acc[j];
}

// ---------------------------------------------------------------------------
extern "C" void kernel_launch(void* const* d_in, const int* in_sizes, int n_in,
                              void* d_out, int out_size)
{
    const float* enc     = (const float*)d_in[0];
    const float* dec     = (const float*)d_in[1];
    const float* W_enc   = (const float*)d_in[2];
    const float* b_enc   = (const float*)d_in[3];
    const float* W_dec   = (const float*)d_in[4];
    const float* b_dec   = (const float*)d_in[5];
    const float* w_alpha = (const float*)d_in[6];
    const float* b_alpha = (const float*)d_in[7];

    float* out = (float*)d_out;
    float* out_res   = out;                        // (B,G,A)
    float* out_alpha = out + (size_t)M2 * AA;      // (B,G,P)

    __half *A1, *B1, *A2, *B2, *attH;
    float *att_dec, *score;
    cudaGetSymbolAddress((void**)&A1, g_A1);
    cudaGetSymbolAddress((void**)&B1, g_B1);
    cudaGetSymbolAddress((void**)&A2, g_A2);
    cudaGetSymbolAddress((void**)&B2, g_B2);
    cudaGetSymbolAddress((void**)&attH, g_att_encH);
    cudaGetSymbolAddress((void**)&att_dec, g_att_dec);
    cudaGetSymbolAddress((void**)&score, g_score);

    cudaFuncSetAttribute(k_gemm_all, cudaFuncAttributeMaxDynamicSharedMemorySize, SMEM_GEMM);

    // 1: all prep (independent blocks)
    k_prep_all<<<3680, 256>>>(enc, dec, W_enc, W_dec, A1, B1, A2, B2);

    // 2: both GEMMs in one wave (392 + 40 CTAs <= 444 slots @ 3/SM)
    k_gemm_all<<<G1_BLOCKS + G2_BLOCKS, 128, SMEM_GEMM>>>(
        A1, B1, A2, B2, b_enc, b_dec, attH, att_dec);

    // 3: scores
    k_score<<<dim3(25, BATCH), 256>>>(w_alpha, b_alpha, score);

    // 4: softmax + weighted sum
    k_soft_wsum<<<dim3(4, BATCH), 256>>>(score, out_alpha, out_res);
}

// round 8
// speedup vs baseline: 4.8077x; 1.1000x over previous
#include <cuda_runtime.h>
#include <cuda_fp16.h>
#include <cstdint>

// Problem constants
#define BATCH 32
#define CC 2048       // channels (K of GEMM1)
#define PP 196        // H*W
#define GG 20         // decoder steps
#define DD 1024       // decode size (K of GEMM2)
#define AA 512        // att size (N of both GEMMs)

#define M1 (BATCH*PP)      // 6272 = 49*128
#define MT1 49
#define M2 (BATCH*GG)      // 640 = 5*128
#define MT2 5
#define KSEC1 64           // 2048/32 k-chunks (GEMM1)
#define KSEC2 32           // 1024/32 (GEMM2)

// GEMM tiling: CTA 128x64, 4 warps (2x2), warp 64x32, chunk K=32.
#define STAGES 3
#define CHUNK_A 8192              // 128 x 32 x 2B
#define CHUNK_B 4096              // 64 x 32 x 2B
#define SROW 80                   // smem row pitch (64B data + 16B pad)
#define SUBT_A (128*SROW)         // 10240
#define SUBT_B (64*SROW)          // 5120
#define STAGE_BYTES (SUBT_A + SUBT_B)    // 15360
#define SMEM_GEMM (STAGES*STAGE_BYTES)   // 46080

#define G1_BLOCKS (8*MT1)         // 392
#define G2_BLOCKS (8*MT2)         // 40

// soft_wsum smem: alpha (20x196 fp32) + att_enc tile (196x128 fp16)
#define SAL_FLOATS (GG*PP)                       // 3920
#define TILE_H2    (PP*64)                       // 12544 half2
#define SMEM_SW    (SAL_FLOATS*4 + TILE_H2*4)    // 65856

// ---------------------------------------------------------------------------
// Scratch
// ---------------------------------------------------------------------------
__device__ __align__(16) __half g_A1[MT1 * KSEC1 * 4096];   // 25.7 MB
__device__ __align__(16) __half g_B1[8   * KSEC1 * 2048];   // 2.1 MB
__device__ __align__(16) __half g_A2[MT2 * KSEC2 * 4096];
__device__ __align__(16) __half g_B2[8   * KSEC2 * 2048];
__device__ __align__(16) __half g_att_encH[M1*AA];   // (B,P,A) fp16, 6.4MB
__device__ float g_att_dec[M2*AA];                   // (B,G,A) fp32
__device__ float g_score[M2*PP];                     // (B,G,P)

// ---------------------------------------------------------------------------
__device__ __forceinline__ uint32_t smem_u32(const void* p) {
    uint32_t a;
    asm("{ .reg .u64 t; cvta.to.shared.u64 t, %1; cvt.u32.u64 %0, t; }" : "=r"(a) : "l"(p));
    return a;
}
__device__ __forceinline__ void cp16(uint32_t saddr, const void* gaddr) {
    asm volatile("cp.async.cg.shared.global [%0], [%1], 16;" :: "r"(saddr), "l"(gaddr));
}
__device__ __forceinline__ void ldm_x4(uint32_t* r, uint32_t addr) {
    asm volatile("ldmatrix.sync.aligned.m8n8.x4.shared.b16 {%0,%1,%2,%3}, [%4];"
        : "=r"(r[0]), "=r"(r[1]), "=r"(r[2]), "=r"(r[3]) : "r"(addr));
}
__device__ __forceinline__ void mma16816(float* c, const uint32_t* a, uint32_t b0, uint32_t b1) {
    asm volatile("mma.sync.aligned.m16n8k16.row.col.f32.f16.f16.f32 "
        "{%0,%1,%2,%3}, {%4,%5,%6,%7}, {%8,%9}, {%0,%1,%2,%3};"
        : "+f"(c[0]), "+f"(c[1]), "+f"(c[2]), "+f"(c[3])
        : "r"(a[0]), "r"(a[1]), "r"(a[2]), "r"(a[3]), "r"(b0), "r"(b1));
}

// ---------------------------------------------------------------------------
// Merged prep kernel.
// ---------------------------------------------------------------------------
__device__ __forceinline__ void prep_B_body(
    const float* __restrict__ W, __half* __restrict__ Bst, int kSec,
    int kc, int nb, int t, float* sm)
{
    #pragma unroll
    for (int i = 0; i < 16; i++) {
        int idx = t + i * 256;
        int kl = idx >> 7, nl = idx & 127;
        sm[kl * 129 + nl] = W[(size_t)(kc * 32 + kl) * AA + nb * 128 + nl];
    }
    __syncthreads();
    #pragma unroll
    for (int i = 0; i < 8; i++) {
        int e2 = t + i * 256;
        int row = e2 >> 4, cp = e2 & 15;
        float x0 = sm[(2*cp)   * 129 + row];
        float x1 = sm[(2*cp+1) * 129 + row];
        int nt = nb * 2 + (row >> 6);
        int rl = row & 63;
        __half2* dst = (__half2*)(Bst + ((size_t)nt * kSec + kc) * 2048);
        dst[rl * 16 + cp] = __halves2half2(__float2half_rn(x0), __float2half_rn(x1));
    }
}

__global__ __launch_bounds__(256) void k_prep_all(
    const float* __restrict__ enc, const float* __restrict__ dec,
    const float* __restrict__ W_enc, const float* __restrict__ W_dec,
    __half* __restrict__ A1, __half* __restrict__ B1,
    __half* __restrict__ A2, __half* __restrict__ B2)
{
    __shared__ float sm[32 * 129];
    const int id = blockIdx.x;
    const int t = threadIdx.x;

    if (id < 3136) {
        const int kc = id & 63, mt = id >> 6;
        #pragma unroll
        for (int i = 0; i < 16; i++) {
            int idx = t + i * 256;            // 4096 = 32c x 128m
            int cl = idx >> 7, ml = idx & 127;
            int m = mt * 128 + ml;
            int b = m / PP, p = m - b * PP;
            sm[cl * 129 + ml] = enc[((size_t)b * CC + (kc * 32 + cl)) * PP + p];
        }
        __syncthreads();
        __half2* hiC = (__half2*)(A1 + ((size_t)mt * KSEC1 + kc) * 4096);
        #pragma unroll
        for (int i = 0; i < 8; i++) {
            int e2 = t + i * 256;             // 2048 half2 = 128r x 16
            int row = e2 >> 4, cp = e2 & 15;
            float x0 = sm[(2*cp)   * 129 + row];
            float x1 = sm[(2*cp+1) * 129 + row];
            hiC[row * 16 + cp] = __halves2half2(__float2half_rn(x0), __float2half_rn(x1));
        }
    } else if (id < 3392) {
        int j = id - 3136;
        prep_B_body(W_enc, B1, KSEC1, j & 63, j >> 6, t, sm);
    } else if (id < 3520) {
        int j = id - 3392;
        prep_B_body(W_dec, B2, KSEC2, j & 31, j >> 5, t, sm);
    } else {
        int j = id - 3520;
        int kc = j & 31, mt = j >> 5;
        __half2* hiC = (__half2*)(A2 + ((size_t)mt * KSEC2 + kc) * 4096);
        #pragma unroll
        for (int i = 0; i < 8; i++) {
            int e2 = t + i * 256;
            int row = e2 >> 4, cp = e2 & 15;
            const float* src = dec + (size_t)(mt * 128 + row) * DD + kc * 32 + 2*cp;
            hiC[row * 16 + cp] = __halves2half2(__float2half_rn(src[0]), __float2half_rn(src[1]));
        }
    }
}

// ---------------------------------------------------------------------------
// Merged fp16 mma.sync GEMM. id < 392: GEMM1 -> fp16; else GEMM2 -> fp32.
// ---------------------------------------------------------------------------
__global__ __launch_bounds__(128, 3) void k_gemm_all(
    const __half* __restrict__ A1g, const __half* __restrict__ B1g,
    const __half* __restrict__ A2g, const __half* __restrict__ B2g,
    const float* __restrict__ b_enc, const float* __restrict__ b_dec,
    __half* __restrict__ out1, float* __restrict__ out2)
{
    extern __shared__ __align__(16) char smem[];
    const int id = blockIdx.x;
    const int t = threadIdx.x;
    const int lane = t & 31, wid = t >> 5;
    const int wm = wid >> 1, wn = wid & 1;        // warp tile (wm*64, wn*32)

    const bool g1 = (id < G1_BLOCKS);
    const int j  = g1 ? id : id - G1_BLOCKS;
    const int mt = j >> 3, nt = j & 7;
    const int kSec = g1 ? KSEC1 : KSEC2;
    const __half* Ast = g1 ? A1g : A2g;
    const __half* Bst = g1 ? B1g : B2g;
    const float* bias = g1 ? b_enc : b_dec;

    const char* Abase = (const char*)(Ast + (size_t)mt * kSec * 4096);
    const char* Bbase = (const char*)(Bst + (size_t)nt * kSec * 2048);
    const uint32_t smem_base = smem_u32(smem);

    auto issue = [&](int kc) {
        const int s = kc % STAGES;
        const char* ga = Abase + (size_t)kc * CHUNK_A;
        const char* gb = Bbase + (size_t)kc * CHUNK_B;
        const uint32_t st = smem_base + s * STAGE_BYTES;
        #pragma unroll
        for (int jj = 0; jj < 4; jj++) {   // A: 512 16B-chunks
            int u = t + jj * 128;
            cp16(st + (u >> 2) * SROW + (u & 3) * 16, ga + u * 16);
        }
        #pragma unroll
        for (int jj = 0; jj < 2; jj++) {   // B: 256 16B-chunks
            int u = t + jj * 128;
            cp16(st + SUBT_A + (u >> 2) * SROW + (u & 3) * 16, gb + u * 16);
        }
        asm volatile("cp.async.commit_group;");
    };

    issue(0); issue(1);

    float c[4][4][4];
    #pragma unroll
    for (int mi = 0; mi < 4; mi++)
        #pragma unroll
        for (int nj = 0; nj < 4; nj++)
            #pragma unroll
            for (int q = 0; q < 4; q++) c[mi][nj][q] = 0.f;

    for (int kc = 0; kc < kSec; kc++) {
        asm volatile("cp.async.wait_group 1;");
        __syncthreads();
        const int s = kc % STAGES;
        const uint32_t st = smem_base + s * STAGE_BYTES;
        const uint32_t aB = st + (wm * 64 + (lane & 15)) * SROW + (lane >> 4) * 16;
        const uint32_t bB = st + SUBT_A + (wn * 32 + (lane & 15)) * SROW + (lane >> 4) * 16;
        #pragma unroll
        for (int ks = 0; ks < 2; ks++) {
            const uint32_t ko = ks * 32;
            uint32_t a[4][4], bh[2][4];
            #pragma unroll
            for (int mi = 0; mi < 4; mi++) ldm_x4(a[mi], aB + mi * 16 * SROW + ko);
            #pragma unroll
            for (int nj = 0; nj < 2; nj++) ldm_x4(bh[nj], bB + nj * 16 * SROW + ko);
            #pragma unroll
            for (int mi = 0; mi < 4; mi++)
                #pragma unroll
                for (int n8 = 0; n8 < 4; n8++) {
                    const int nj = n8 >> 1, hl = n8 & 1;
                    mma16816(c[mi][n8], a[mi], bh[nj][hl], bh[nj][hl + 2]);
                }
        }
        if (kc + 2 < kSec) issue(kc + 2);
        else asm volatile("cp.async.commit_group;");
    }

    // epilogue
    const int r0b = mt * 128 + wm * 64 + (lane >> 2);
    const int ncb = nt * 64 + wn * 32 + (lane & 3) * 2;
    #pragma unroll
    for (int mi = 0; mi < 4; mi++) {
        #pragma unroll
        for (int n8 = 0; n8 < 4; n8++) {
            const int n = ncb + n8 * 8;
            const float b0 = bias[n], b1 = bias[n + 1];
            const size_t o0 = (size_t)(r0b + mi * 16) * AA + n;
            if (g1) {
                *(__half2*)(out1 + o0) =
                    __floats2half2_rn(c[mi][n8][0] + b0, c[mi][n8][1] + b1);
                *(__half2*)(out1 + o0 + 8 * AA) =
                    __floats2half2_rn(c[mi][n8][2] + b0, c[mi][n8][3] + b1);
            } else {
                float2 v0 = { c[mi][n8][0] + b0, c[mi][n8][1] + b1 };
                float2 v1 = { c[mi][n8][2] + b0, c[mi][n8][3] + b1 };
                *(float2*)(out2 + o0) = v0;
                *(float2*)(out2 + o0 + 8 * AA) = v1;
            }
        }
    }
}

// ---------------------------------------------------------------------------
// K3a: scores. Block = (p-tile of 8 warps, b). att_enc fp16, reused over 20 g.
// ---------------------------------------------------------------------------
__global__ __launch_bounds__(256) void k_score(
    const float* __restrict__ w_alpha, const float* __restrict__ b_alpha,
    float* __restrict__ score)
{
    __shared__ float sdec[GG * AA];   // 40KB
    __shared__ float sw_[AA];
    const int b = blockIdx.y;
    const int t = threadIdx.x, warp = t >> 5, lane = t & 31;

    const float* dptr = g_att_dec + (size_t)b * GG * AA;
    for (int i = t; i < GG * AA; i += 256) sdec[i] = dptr[i];
    for (int i = t; i < AA; i += 256) sw_[i] = w_alpha[i];
    __syncthreads();

    const int p = blockIdx.x * 8 + warp;
    if (p >= PP) return;
    const float ba = b_alpha[0];
    const __half2* ep = (const __half2*)(g_att_encH + ((size_t)b * PP + p) * AA);

    float2 e[8];
    #pragma unroll
    for (int i = 0; i < 8; i++) e[i] = __half22float2(ep[lane + 32 * i]);

    for (int g = 0; g < GG; g++) {
        float s = 0.f;
        const float* dg = sdec + g * AA;
        #pragma unroll
        for (int i = 0; i < 8; i++) {
            int a = 2 * (lane + 32 * i);
            float2 d2 = *(const float2*)&dg[a];
            float2 w2 = *(const float2*)&sw_[a];
            s = fmaf(fmaxf(e[i].x + d2.x, 0.f), w2.x, s);
            s = fmaf(fmaxf(e[i].y + d2.y, 0.f), w2.y, s);
        }
        #pragma unroll
        for (int o = 16; o > 0; o >>= 1)
            s += __shfl_xor_sync(0xffffffffu, s, o);
        if (lane == 0) score[((size_t)b * GG + g) * PP + p] = s + ba;
    }
}

// ---------------------------------------------------------------------------
// K3b (fused): stage att_enc tile in smem, softmax, weighted sum from smem.
// grid (4 a-chunks, B), 256 threads; chunk 0 also writes alpha.
// ---------------------------------------------------------------------------
__global__ __launch_bounds__(256) void k_soft_wsum(
    const float* __restrict__ score, float* __restrict__ out_alpha,
    float* __restrict__ out_res)
{
    extern __shared__ __align__(16) char dsm[];
    float*   sal  = (float*)dsm;                         // 20 x 196
    __half2* tile = (__half2*)(dsm + SAL_FLOATS * 4);    // 196 x 64 half2

    const int b = blockIdx.y, a0 = blockIdx.x * 128;
    const int t = threadIdx.x, warp = t >> 5, lane = t & 31;

    // stage att_enc tile: rows of 256B, uint4 loads, MLP ~12
    {
        const char* src = (const char*)(g_att_encH + (size_t)b * PP * AA + a0);
        uint4* dst = (uint4*)tile;
        #pragma unroll
        for (int i = 0; i < 13; i++) {
            int u = t + i * 256;                         // 3136 16B-chunks
            if (u < PP * 16) {
                int p = u >> 4, c = u & 15;
                dst[u] = *(const uint4*)(src + (size_t)p * AA * 2 + c * 16);
            }
        }
    }
    // stage scores
    const float* sp = score + (size_t)b * GG * PP;
    for (int i = t; i < GG * PP; i += 256) sal[i] = sp[i];
    __syncthreads();

    // softmax: warp per g (20 rows, 8 warps)
    for (int g = warp; g < GG; g += 8) {
        float* row = sal + g * PP;
        float m = -1e30f;
        for (int p = lane; p < PP; p += 32) m = fmaxf(m, row[p]);
        #pragma unroll
        for (int o = 16; o > 0; o >>= 1)
            m = fmaxf(m, __shfl_xor_sync(0xffffffffu, m, o));
        float sum = 0.f;
        for (int p = lane; p < PP; p += 32) {
            float ex = __expf(row[p] - m);
            row[p] = ex;
            sum += ex;
        }
        #pragma unroll
        for (int o = 16; o > 0; o >>= 1)
            sum += __shfl_xor_sync(0xffffffffu, sum, o);
        const float inv = 1.f / sum;
        for (int p = lane; p < PP; p += 32) row[p] *= inv;
    }
    __syncthreads();

    if (blockIdx.x == 0) {
        float* ao = out_alpha + (size_t)b * GG * PP;
        for (int i = t; i < GG * PP; i += 256) ao[i] = sal[i];
    }

    // weighted sum: thread = (half2 index al2 0..63, g-quarter h 0..3), 5 g each
    const int al2 = t & 63, h = t >> 6;
    float2 acc[5];
    #pragma unroll
    for (int j = 0; j < 5; j++) acc[j] = make_float2(0.f, 0.f);

    const float* salh = sal + h * 5 * PP;
    #pragma unroll 4
    for (int p = 0; p < PP; p++) {
        float2 v = __half22float2(tile[p * 64 + al2]);
        #pragma unroll
        for (int j = 0; j < 5; j++) {
            float al = salh[j * PP + p];
            acc[j].x = fmaf(al, v.x, acc[j].x);
            acc[j].y = fmaf(al, v.y, acc[j].y);
        }
    }
    #pragma unroll
    for (int j = 0; j < 5; j++)
        *(float2*)&out_res[((size_t)b * GG + h * 5 + j) * AA + a0 + 2 * al2] = acc[j];
}

// ---------------------------------------------------------------------------
extern "C" void kernel_launch(void* const* d_in, const int* in_sizes, int n_in,
                              void* d_out, int out_size)
{
    const float* enc     = (const float*)d_in[0];
    const float* dec     = (const float*)d_in[1];
    const float* W_enc   = (const float*)d_in[2];
    const float* b_enc   = (const float*)d_in[3];
    const float* W_dec   = (const float*)d_in[4];
    const float* b_dec   = (const float*)d_in[5];
    const float* w_alpha = (const float*)d_in[6];
    const float* b_alpha = (const float*)d_in[7];

    float* out = (float*)d_out;
    float* out_res   = out;                        // (B,G,A)
    float* out_alpha = out + (size_t)M2 * AA;      // (B,G,P)

    __half *A1, *B1, *A2, *B2, *attH;
    float *att_dec, *score;
    cudaGetSymbolAddress((void**)&A1, g_A1);
    cudaGetSymbolAddress((void**)&B1, g_B1);
    cudaGetSymbolAddress((void**)&A2, g_A2);
    cudaGetSymbolAddress((void**)&B2, g_B2);
    cudaGetSymbolAddress((void**)&attH, g_att_encH);
    cudaGetSymbolAddress((void**)&att_dec, g_att_dec);
    cudaGetSymbolAddress((void**)&score, g_score);

    cudaFuncSetAttribute(k_gemm_all,  cudaFuncAttributeMaxDynamicSharedMemorySize, SMEM_GEMM);
    cudaFuncSetAttribute(k_soft_wsum, cudaFuncAttributeMaxDynamicSharedMemorySize, SMEM_SW);

    // 1: all prep (independent blocks)
    k_prep_all<<<3680, 256>>>(enc, dec, W_enc, W_dec, A1, B1, A2, B2);

    // 2: both GEMMs in one wave
    k_gemm_all<<<G1_BLOCKS + G2_BLOCKS, 128, SMEM_GEMM>>>(
        A1, B1, A2, B2, b_enc, b_dec, attH, att_dec);

    // 3: scores
    k_score<<<dim3(25, BATCH), 256>>>(w_alpha, b_alpha, score);

    // 4: softmax + weighted sum (smem-staged)
    k_soft_wsum<<<dim3(4, BATCH), 256, SMEM_SW>>>(score, out_alpha, out_res);
}

// round 9
// speedup vs baseline: 4.8863x; 1.0164x over previous
#include <cuda_runtime.h>
#include <cuda_fp16.h>
#include <cstdint>

// Problem constants
#define BATCH 32
#define CC 2048       // channels (K of GEMM1)
#define PP 196        // H*W
#define GG 20         // decoder steps
#define DD 1024       // decode size (K of GEMM2)
#define AA 512        // att size (N of both GEMMs)

#define M1 (BATCH*PP)      // 6272 = 49*128
#define MT1 49
#define M2 (BATCH*GG)      // 640 = 5*128
#define MT2 5
#define KSEC1 64           // 2048/32 k-chunks (GEMM1)
#define KSEC2 32           // 1024/32 (GEMM2)

// GEMM tiling: CTA 128x64, 4 warps (2x2), warp 64x32, chunk K=32.
#define STAGES 3
#define CHUNK_A 8192              // 128 x 32 x 2B
#define CHUNK_B 4096              // 64 x 32 x 2B
#define SROW 80                   // smem row pitch (64B data + 16B pad)
#define SUBT_A (128*SROW)         // 10240
#define SUBT_B (64*SROW)          // 5120
#define STAGE_BYTES (SUBT_A + SUBT_B)    // 15360
#define SMEM_GEMM (STAGES*STAGE_BYTES)   // 46080

#define G1_BLOCKS (8*MT1)         // 392
#define G2_BLOCKS (8*MT2)         // 40

// ---------------------------------------------------------------------------
// Scratch
// ---------------------------------------------------------------------------
__device__ __align__(16) __half g_A1[MT1 * KSEC1 * 4096];   // 25.7 MB
__device__ __align__(16) __half g_B1[8   * KSEC1 * 2048];   // 2.1 MB
__device__ __align__(16) __half g_A2[MT2 * KSEC2 * 4096];
__device__ __align__(16) __half g_B2[8   * KSEC2 * 2048];
__device__ __align__(16) __half g_att_encH[M1*AA];   // (B,P,A) fp16, 6.4MB
__device__ float g_att_dec[M2*AA];                   // (B,G,A) fp32
__device__ float g_score[M2*PP];                     // (B,G,P)

// ---------------------------------------------------------------------------
__device__ __forceinline__ uint32_t smem_u32(const void* p) {
    uint32_t a;
    asm("{ .reg .u64 t; cvta.to.shared.u64 t, %1; cvt.u32.u64 %0, t; }" : "=r"(a) : "l"(p));
    return a;
}
__device__ __forceinline__ void cp16(uint32_t saddr, const void* gaddr) {
    asm volatile("cp.async.cg.shared.global [%0], [%1], 16;" :: "r"(saddr), "l"(gaddr));
}
__device__ __forceinline__ void ldm_x4(uint32_t* r, uint32_t addr) {
    asm volatile("ldmatrix.sync.aligned.m8n8.x4.shared.b16 {%0,%1,%2,%3}, [%4];"
        : "=r"(r[0]), "=r"(r[1]), "=r"(r[2]), "=r"(r[3]) : "r"(addr));
}
__device__ __forceinline__ void mma16816(float* c, const uint32_t* a, uint32_t b0, uint32_t b1) {
    asm volatile("mma.sync.aligned.m16n8k16.row.col.f32.f16.f16.f32 "
        "{%0,%1,%2,%3}, {%4,%5,%6,%7}, {%8,%9}, {%0,%1,%2,%3};"
        : "+f"(c[0]), "+f"(c[1]), "+f"(c[2]), "+f"(c[3])
        : "r"(a[0]), "r"(a[1]), "r"(a[2]), "r"(a[3]), "r"(b0), "r"(b1));
}

// ---------------------------------------------------------------------------
// Merged prep kernel.
// ---------------------------------------------------------------------------
__device__ __forceinline__ void prep_B_body(
    const float* __restrict__ W, __half* __restrict__ Bst, int kSec,
    int kc, int nb, int t, float* sm)
{
    #pragma unroll
    for (int i = 0; i < 16; i++) {
        int idx = t + i * 256;
        int kl = idx >> 7, nl = idx & 127;
        sm[kl * 129 + nl] = W[(size_t)(kc * 32 + kl) * AA + nb * 128 + nl];
    }
    __syncthreads();
    #pragma unroll
    for (int i = 0; i < 8; i++) {
        int e2 = t + i * 256;
        int row = e2 >> 4, cp = e2 & 15;
        float x0 = sm[(2*cp)   * 129 + row];
        float x1 = sm[(2*cp+1) * 129 + row];
        int nt = nb * 2 + (row >> 6);
        int rl = row & 63;
        __half2* dst = (__half2*)(Bst + ((size_t)nt * kSec + kc) * 2048);
        dst[rl * 16 + cp] = __halves2half2(__float2half_rn(x0), __float2half_rn(x1));
    }
}

__global__ __launch_bounds__(256) void k_prep_all(
    const float* __restrict__ enc, const float* __restrict__ dec,
    const float* __restrict__ W_enc, const float* __restrict__ W_dec,
    __half* __restrict__ A1, __half* __restrict__ B1,
    __half* __restrict__ A2, __half* __restrict__ B2)
{
    __shared__ float sm[32 * 129];
    const int id = blockIdx.x;
    const int t = threadIdx.x;

    if (id < 3136) {
        const int kc = id & 63, mt = id >> 6;
        #pragma unroll
        for (int i = 0; i < 16; i++) {
            int idx = t + i * 256;            // 4096 = 32c x 128m
            int cl = idx >> 7, ml = idx & 127;
            int m = mt * 128 + ml;
            int b = m / PP, p = m - b * PP;
            sm[cl * 129 + ml] = enc[((size_t)b * CC + (kc * 32 + cl)) * PP + p];
        }
        __syncthreads();
        __half2* hiC = (__half2*)(A1 + ((size_t)mt * KSEC1 + kc) * 4096);
        #pragma unroll
        for (int i = 0; i < 8; i++) {
            int e2 = t + i * 256;             // 2048 half2 = 128r x 16
            int row = e2 >> 4, cp = e2 & 15;
            float x0 = sm[(2*cp)   * 129 + row];
            float x1 = sm[(2*cp+1) * 129 + row];
            hiC[row * 16 + cp] = __halves2half2(__float2half_rn(x0), __float2half_rn(x1));
        }
    } else if (id < 3392) {
        int j = id - 3136;
        prep_B_body(W_enc, B1, KSEC1, j & 63, j >> 6, t, sm);
    } else if (id < 3520) {
        int j = id - 3392;
        prep_B_body(W_dec, B2, KSEC2, j & 31, j >> 5, t, sm);
    } else {
        int j = id - 3520;
        int kc = j & 31, mt = j >> 5;
        __half2* hiC = (__half2*)(A2 + ((size_t)mt * KSEC2 + kc) * 4096);
        #pragma unroll
        for (int i = 0; i < 8; i++) {
            int e2 = t + i * 256;
            int row = e2 >> 4, cp = e2 & 15;
            const float* src = dec + (size_t)(mt * 128 + row) * DD + kc * 32 + 2*cp;
            hiC[row * 16 + cp] = __halves2half2(__float2half_rn(src[0]), __float2half_rn(src[1]));
        }
    }
}

// ---------------------------------------------------------------------------
// Merged fp16 mma.sync GEMM. id < 392: GEMM1 -> fp16; else GEMM2 -> fp32.
// ---------------------------------------------------------------------------
__global__ __launch_bounds__(128, 3) void k_gemm_all(
    const __half* __restrict__ A1g, const __half* __restrict__ B1g,
    const __half* __restrict__ A2g, const __half* __restrict__ B2g,
    const float* __restrict__ b_enc, const float* __restrict__ b_dec,
    __half* __restrict__ out1, float* __restrict__ out2)
{
    extern __shared__ __align__(16) char smem[];
    const int id = blockIdx.x;
    const int t = threadIdx.x;
    const int lane = t & 31, wid = t >> 5;
    const int wm = wid >> 1, wn = wid & 1;        // warp tile (wm*64, wn*32)

    const bool g1 = (id < G1_BLOCKS);
    const int j  = g1 ? id : id - G1_BLOCKS;
    const int mt = j >> 3, nt = j & 7;
    const int kSec = g1 ? KSEC1 : KSEC2;
    const __half* Ast = g1 ? A1g : A2g;
    const __half* Bst = g1 ? B1g : B2g;
    const float* bias = g1 ? b_enc : b_dec;

    const char* Abase = (const char*)(Ast + (size_t)mt * kSec * 4096);
    const char* Bbase = (const char*)(Bst + (size_t)nt * kSec * 2048);
    const uint32_t smem_base = smem_u32(smem);

    auto issue = [&](int kc) {
        const int s = kc % STAGES;
        const char* ga = Abase + (size_t)kc * CHUNK_A;
        const char* gb = Bbase + (size_t)kc * CHUNK_B;
        const uint32_t st = smem_base + s * STAGE_BYTES;
        #pragma unroll
        for (int jj = 0; jj < 4; jj++) {   // A: 512 16B-chunks
            int u = t + jj * 128;
            cp16(st + (u >> 2) * SROW + (u & 3) * 16, ga + u * 16);
        }
        #pragma unroll
        for (int jj = 0; jj < 2; jj++) {   // B: 256 16B-chunks
            int u = t + jj * 128;
            cp16(st + SUBT_A + (u >> 2) * SROW + (u & 3) * 16, gb + u * 16);
        }
        asm volatile("cp.async.commit_group;");
    };

    issue(0); issue(1);

    float c[4][4][4];
    #pragma unroll
    for (int mi = 0; mi < 4; mi++)
        #pragma unroll
        for (int nj = 0; nj < 4; nj++)
            #pragma unroll
            for (int q = 0; q < 4; q++) c[mi][nj][q] = 0.f;

    for (int kc = 0; kc < kSec; kc++) {
        asm volatile("cp.async.wait_group 1;");
        __syncthreads();
        const int s = kc % STAGES;
        const uint32_t st = smem_base + s * STAGE_BYTES;
        const uint32_t aB = st + (wm * 64 + (lane & 15)) * SROW + (lane >> 4) * 16;
        const uint32_t bB = st + SUBT_A + (wn * 32 + (lane & 15)) * SROW + (lane >> 4) * 16;
        #pragma unroll
        for (int ks = 0; ks < 2; ks++) {
            const uint32_t ko = ks * 32;
            uint32_t a[4][4], bh[2][4];
            #pragma unroll
            for (int mi = 0; mi < 4; mi++) ldm_x4(a[mi], aB + mi * 16 * SROW + ko);
            #pragma unroll
            for (int nj = 0; nj < 2; nj++) ldm_x4(bh[nj], bB + nj * 16 * SROW + ko);
            #pragma unroll
            for (int mi = 0; mi < 4; mi++)
                #pragma unroll
                for (int n8 = 0; n8 < 4; n8++) {
                    const int nj = n8 >> 1, hl = n8 & 1;
                    mma16816(c[mi][n8], a[mi], bh[nj][hl], bh[nj][hl + 2]);
                }
        }
        if (kc + 2 < kSec) issue(kc + 2);
        else asm volatile("cp.async.commit_group;");
    }

    // epilogue
    const int r0b = mt * 128 + wm * 64 + (lane >> 2);
    const int ncb = nt * 64 + wn * 32 + (lane & 3) * 2;
    #pragma unroll
    for (int mi = 0; mi < 4; mi++) {
        #pragma unroll
        for (int n8 = 0; n8 < 4; n8++) {
            const int n = ncb + n8 * 8;
            const float b0 = bias[n], b1 = bias[n + 1];
            const size_t o0 = (size_t)(r0b + mi * 16) * AA + n;
            if (g1) {
                *(__half2*)(out1 + o0) =
                    __floats2half2_rn(c[mi][n8][0] + b0, c[mi][n8][1] + b1);
                *(__half2*)(out1 + o0 + 8 * AA) =
                    __floats2half2_rn(c[mi][n8][2] + b0, c[mi][n8][3] + b1);
            } else {
                float2 v0 = { c[mi][n8][0] + b0, c[mi][n8][1] + b1 };
                float2 v1 = { c[mi][n8][2] + b0, c[mi][n8][3] + b1 };
                *(float2*)(out2 + o0) = v0;
                *(float2*)(out2 + o0 + 8 * AA) = v1;
            }
        }
    }
}

// ---------------------------------------------------------------------------
// K3a: scores. Block = (p-tile of 8 warps, b). d in half2 smem (1 wavefront
// per load), w hoisted into registers. e in registers, reused over 20 g.
// ---------------------------------------------------------------------------
__global__ __launch_bounds__(256) void k_score(
    const float* __restrict__ w_alpha, const float* __restrict__ b_alpha,
    float* __restrict__ score)
{
    __shared__ __half2 sdec[GG * AA / 2];   // 20KB
    __shared__ float sw_[AA];               // 2KB
    const int b = blockIdx.y;
    const int t = threadIdx.x, warp = t >> 5, lane = t & 31;

    const float* dptr = g_att_dec + (size_t)b * GG * AA;
    for (int i = t; i < GG * AA / 2; i += 256) {
        float2 d2 = *(const float2*)&dptr[2 * i];
        sdec[i] = __floats2half2_rn(d2.x, d2.y);
    }
    for (int i = t; i < AA; i += 256) sw_[i] = w_alpha[i];
    __syncthreads();

    const int p = blockIdx.x * 8 + warp;
    if (p >= PP) return;
    const float ba = b_alpha[0];
    const __half2* ep = (const __half2*)(g_att_encH + ((size_t)b * PP + p) * AA);

    float2 e[8], w[8];
    #pragma unroll
    for (int i = 0; i < 8; i++) {
        e[i] = __half22float2(ep[lane + 32 * i]);
        w[i] = *(const float2*)&sw_[2 * (lane + 32 * i)];
    }

    for (int g = 0; g < GG; g++) {
        float s = 0.f;
        const __half2* dg = sdec + g * (AA / 2);
        #pragma unroll
        for (int i = 0; i < 8; i++) {
            float2 d2 = __half22float2(dg[lane + 32 * i]);
            s = fmaf(fmaxf(e[i].x + d2.x, 0.f), w[i].x, s);
            s = fmaf(fmaxf(e[i].y + d2.y, 0.f), w[i].y, s);
        }
        #pragma unroll
        for (int o = 16; o > 0; o >>= 1)
            s += __shfl_xor_sync(0xffffffffu, s, o);
        if (lane == 0) score[((size_t)b * GG + g) * PP + p] = s + ba;
    }
}

// ---------------------------------------------------------------------------
// K3b (fused): cp.async-stage 196x64 att_enc tile (overlapped with score load
// + softmax), then wsum with float4 alpha loads.
// grid (8 a-chunks, B), 320 threads; chunk 0 writes alpha.
// ---------------------------------------------------------------------------
__global__ __launch_bounds__(320) void k_soft_wsum(
    const float* __restrict__ score, float* __restrict__ out_alpha,
    float* __restrict__ out_res)
{
    __shared__ __align__(16) float sal[GG * PP];      // 15.7KB
    __shared__ __align__(16) __half2 tile[PP * 32];   // 25KB: [p][32 half2]

    const int b = blockIdx.y, a0 = blockIdx.x * 64;
    const int t = threadIdx.x, warp = t >> 5, lane = t & 31;

    // stage tile via cp.async (1568 16B chunks), overlapped with softmax
    {
        const char* src = (const char*)(g_att_encH + (size_t)b * PP * AA + a0);
        const uint32_t tb = smem_u32(tile);
        #pragma unroll
        for (int i = 0; i < 5; i++) {
            int u = t + i * 320;
            if (u < PP * 8) {
                int p = u >> 3, c = u & 7;
                cp16(tb + u * 16, src + (size_t)p * AA * 2 + c * 16);
            }
        }
        asm volatile("cp.async.commit_group;");
    }

    // stage scores
    const float* sp = score + (size_t)b * GG * PP;
    for (int i = t; i < GG * PP; i += 320) sal[i] = sp[i];
    __syncthreads();

    // softmax: warp per g (20 rows, 10 warps -> 2 rounds)
    for (int g = warp; g < GG; g += 10) {
        float* row = sal + g * PP;
        float m = -1e30f;
        for (int p = lane; p < PP; p += 32) m = fmaxf(m, row[p]);
        #pragma unroll
        for (int o = 16; o > 0; o >>= 1)
            m = fmaxf(m, __shfl_xor_sync(0xffffffffu, m, o));
        float sum = 0.f;
        for (int p = lane; p < PP; p += 32) {
            float ex = __expf(row[p] - m);
            row[p] = ex;
            sum += ex;
        }
        #pragma unroll
        for (int o = 16; o > 0; o >>= 1)
            sum += __shfl_xor_sync(0xffffffffu, sum, o);
        const float inv = 1.f / sum;
        for (int p = lane; p < PP; p += 32) row[p] *= inv;
    }
    asm volatile("cp.async.wait_group 0;");
    __syncthreads();

    if (blockIdx.x == 0) {
        float* ao = out_alpha + (size_t)b * GG * PP;
        for (int i = t; i < GG * PP; i += 320) ao[i] = sal[i];
    }

    // wsum: thread = (al2 = t&31, h = t>>5 in 0..9, g = 2h, 2h+1)
    const int al2 = t & 31, h = warp;
    const int g0 = 2 * h, g1 = 2 * h + 1;
    float2 acc0 = make_float2(0.f, 0.f), acc1 = make_float2(0.f, 0.f);
    const float4* s40 = (const float4*)(sal + g0 * PP);
    const float4* s41 = (const float4*)(sal + g1 * PP);

    #pragma unroll 7
    for (int p4 = 0; p4 < PP / 4; p4++) {
        float4 A0 = s40[p4], A1 = s41[p4];
        float2 v0 = __half22float2(tile[(4 * p4 + 0) * 32 + al2]);
        float2 v1 = __half22float2(tile[(4 * p4 + 1) * 32 + al2]);
        float2 v2 = __half22float2(tile[(4 * p4 + 2) * 32 + al2]);
        float2 v3 = __half22float2(tile[(4 * p4 + 3) * 32 + al2]);
        acc0.x = fmaf(A0.x, v0.x, acc0.x); acc0.y = fmaf(A0.x, v0.y, acc0.y);
        acc0.x = fmaf(A0.y, v1.x, acc0.x); acc0.y = fmaf(A0.y, v1.y, acc0.y);
        acc0.x = fmaf(A0.z, v2.x, acc0.x); acc0.y = fmaf(A0.z, v2.y, acc0.y);
        acc0.x = fmaf(A0.w, v3.x, acc0.x); acc0.y = fmaf(A0.w, v3.y, acc0.y);
        acc1.x = fmaf(A1.x, v0.x, acc1.x); acc1.y = fmaf(A1.x, v0.y, acc1.y);
        acc1.x = fmaf(A1.y, v1.x, acc1.x); acc1.y = fmaf(A1.y, v1.y, acc1.y);
        acc1.x = fmaf(A1.z, v2.x, acc1.x); acc1.y = fmaf(A1.z, v2.y, acc1.y);
        acc1.x = fmaf(A1.w, v3.x, acc1.x); acc1.y = fmaf(A1.w, v3.y, acc1.y);
    }
    *(float2*)&out_res[((size_t)b * GG + g0) * AA + a0 + 2 * al2] = acc0;
    *(float2*)&out_res[((size_t)b * GG + g1) * AA + a0 + 2 * al2] = acc1;
}

// ---------------------------------------------------------------------------
extern "C" void kernel_launch(void* const* d_in, const int* in_sizes, int n_in,
                              void* d_out, int out_size)
{
    const float* enc     = (const float*)d_in[0];
    const float* dec     = (const float*)d_in[1];
    const float* W_enc   = (const float*)d_in[2];
    const float* b_enc   = (const float*)d_in[3];
    const float* W_dec   = (const float*)d_in[4];
    const float* b_dec   = (const float*)d_in[5];
    const float* w_alpha = (const float*)d_in[6];
    const float* b_alpha = (const float*)d_in[7];

    float* out = (float*)d_out;
    float* out_res   = out;                        // (B,G,A)
    float* out_alpha = out + (size_t)M2 * AA;      // (B,G,P)

    __half *A1, *B1, *A2, *B2, *attH;
    float *att_dec, *score;
    cudaGetSymbolAddress((void**)&A1, g_A1);
    cudaGetSymbolAddress((void**)&B1, g_B1);
    cudaGetSymbolAddress((void**)&A2, g_A2);
    cudaGetSymbolAddress((void**)&B2, g_B2);
    cudaGetSymbolAddress((void**)&attH, g_att_encH);
    cudaGetSymbolAddress((void**)&att_dec, g_att_dec);
    cudaGetSymbolAddress((void**)&score, g_score);

    cudaFuncSetAttribute(k_gemm_all, cudaFuncAttributeMaxDynamicSharedMemorySize, SMEM_GEMM);

    // 1: all prep (independent blocks)
    k_prep_all<<<3680, 256>>>(enc, dec, W_enc, W_dec, A1, B1, A2, B2);

    // 2: both GEMMs in one wave
    k_gemm_all<<<G1_BLOCKS + G2_BLOCKS, 128, SMEM_GEMM>>>(
        A1, B1, A2, B2, b_enc, b_dec, attH, att_dec);

    // 3: scores
    k_score<<<dim3(25, BATCH), 256>>>(w_alpha, b_alpha, score);

    // 4: softmax + weighted sum (cp.async staged, 8 a-chunks)
    k_soft_wsum<<<dim3(8, BATCH), 320>>>(score, out_alpha, out_res);
}

// round 10
// speedup vs baseline: 5.0831x; 1.0403x over previous
#include <cuda_runtime.h>
#include <cuda_fp16.h>
#include <cstdint>

// Problem constants
#define BATCH 32
#define CC 2048       // channels (K of GEMM1)
#define PP 196        // H*W
#define GG 20         // decoder steps
#define DD 1024       // decode size (K of GEMM2)
#define AA 512        // att size (N of both GEMMs)

#define M1 (BATCH*PP)      // 6272 = 49*128
#define MT1 49
#define M2 (BATCH*GG)      // 640 = 5*128
#define MT2 5
#define KSEC1 64           // 2048/32 k-chunks (GEMM1)
#define KSEC2 32           // 1024/32 (GEMM2)

// GEMM tiling: CTA 128x64, 4 warps (2x2), warp 64x32, chunk K=32.
#define STAGES 4
#define CHUNK_A 8192              // 128 x 32 x 2B
#define CHUNK_B 4096              // 64 x 32 x 2B
#define SROW 80                   // smem row pitch (64B data + 16B pad)
#define SUBT_A (128*SROW)         // 10240
#define SUBT_B (64*SROW)          // 5120
#define STAGE_BYTES (SUBT_A + SUBT_B)    // 15360
#define SMEM_GEMM (STAGES*STAGE_BYTES)   // 61440

#define G1_BLOCKS (8*MT1)         // 392
#define G2_BLOCKS (8*MT2)         // 40

// ---------------------------------------------------------------------------
// Scratch
// ---------------------------------------------------------------------------
__device__ __align__(16) __half g_A1[MT1 * KSEC1 * 4096];   // 25.7 MB
__device__ __align__(16) __half g_B1[8   * KSEC1 * 2048];   // 2.1 MB
__device__ __align__(16) __half g_A2[MT2 * KSEC2 * 4096];
__device__ __align__(16) __half g_B2[8   * KSEC2 * 2048];
__device__ __align__(16) __half g_att_encH[M1*AA];   // (B,P,A) fp16, 6.4MB
__device__ float g_att_dec[M2*AA];                   // (B,G,A) fp32
__device__ float g_score[M2*PP];                     // (B,G,P)

// ---------------------------------------------------------------------------
__device__ __forceinline__ uint32_t smem_u32(const void* p) {
    uint32_t a;
    asm("{ .reg .u64 t; cvta.to.shared.u64 t, %1; cvt.u32.u64 %0, t; }" : "=r"(a) : "l"(p));
    return a;
}
__device__ __forceinline__ void cp16(uint32_t saddr, const void* gaddr) {
    asm volatile("cp.async.cg.shared.global [%0], [%1], 16;" :: "r"(saddr), "l"(gaddr));
}
__device__ __forceinline__ void ldm_x4(uint32_t* r, uint32_t addr) {
    asm volatile("ldmatrix.sync.aligned.m8n8.x4.shared.b16 {%0,%1,%2,%3}, [%4];"
        : "=r"(r[0]), "=r"(r[1]), "=r"(r[2]), "=r"(r[3]) : "r"(addr));
}
__device__ __forceinline__ void mma16816(float* c, const uint32_t* a, uint32_t b0, uint32_t b1) {
    asm volatile("mma.sync.aligned.m16n8k16.row.col.f32.f16.f16.f32 "
        "{%0,%1,%2,%3}, {%4,%5,%6,%7}, {%8,%9}, {%0,%1,%2,%3};"
        : "+f"(c[0]), "+f"(c[1]), "+f"(c[2]), "+f"(c[3])
        : "r"(a[0]), "r"(a[1]), "r"(a[2]), "r"(a[3]), "r"(b0), "r"(b1));
}

// ---------------------------------------------------------------------------
// Merged prep kernel.
// ---------------------------------------------------------------------------
__device__ __forceinline__ void prep_B_body(
    const float* __restrict__ W, __half* __restrict__ Bst, int kSec,
    int kc, int nb, int t, float* sm)
{
    #pragma unroll
    for (int i = 0; i < 16; i++) {
        int idx = t + i * 256;
        int kl = idx >> 7, nl = idx & 127;
        sm[kl * 129 + nl] = W[(size_t)(kc * 32 + kl) * AA + nb * 128 + nl];
    }
    __syncthreads();
    #pragma unroll
    for (int i = 0; i < 8; i++) {
        int e2 = t + i * 256;
        int row = e2 >> 4, cp = e2 & 15;
        float x0 = sm[(2*cp)   * 129 + row];
        float x1 = sm[(2*cp+1) * 129 + row];
        int nt = nb * 2 + (row >> 6);
        int rl = row & 63;
        __half2* dst = (__half2*)(Bst + ((size_t)nt * kSec + kc) * 2048);
        dst[rl * 16 + cp] = __halves2half2(__float2half_rn(x0), __float2half_rn(x1));
    }
}

__global__ __launch_bounds__(256) void k_prep_all(
    const float* __restrict__ enc, const float* __restrict__ dec,
    const float* __restrict__ W_enc, const float* __restrict__ W_dec,
    __half* __restrict__ A1, __half* __restrict__ B1,
    __half* __restrict__ A2, __half* __restrict__ B2)
{
    __shared__ float sm[32 * 129];
    const int id = blockIdx.x;
    const int t = threadIdx.x;

    if (id < 3136) {
        const int kc = id & 63, mt = id >> 6;
        #pragma unroll
        for (int i = 0; i < 16; i++) {
            int idx = t + i * 256;            // 4096 = 32c x 128m
            int cl = idx >> 7, ml = idx & 127;
            int m = mt * 128 + ml;
            int b = m / PP, p = m - b * PP;
            sm[cl * 129 + ml] = enc[((size_t)b * CC + (kc * 32 + cl)) * PP + p];
        }
        __syncthreads();
        __half2* hiC = (__half2*)(A1 + ((size_t)mt * KSEC1 + kc) * 4096);
        #pragma unroll
        for (int i = 0; i < 8; i++) {
            int e2 = t + i * 256;             // 2048 half2 = 128r x 16
            int row = e2 >> 4, cp = e2 & 15;
            float x0 = sm[(2*cp)   * 129 + row];
            float x1 = sm[(2*cp+1) * 129 + row];
            hiC[row * 16 + cp] = __halves2half2(__float2half_rn(x0), __float2half_rn(x1));
        }
    } else if (id < 3392) {
        int j = id - 3136;
        prep_B_body(W_enc, B1, KSEC1, j & 63, j >> 6, t, sm);
    } else if (id < 3520) {
        int j = id - 3392;
        prep_B_body(W_dec, B2, KSEC2, j & 31, j >> 5, t, sm);
    } else {
        int j = id - 3520;
        int kc = j & 31, mt = j >> 5;
        __half2* hiC = (__half2*)(A2 + ((size_t)mt * KSEC2 + kc) * 4096);
        #pragma unroll
        for (int i = 0; i < 8; i++) {
            int e2 = t + i * 256;
            int row = e2 >> 4, cp = e2 & 15;
            const float* src = dec + (size_t)(mt * 128 + row) * DD + kc * 32 + 2*cp;
            hiC[row * 16 + cp] = __halves2half2(__float2half_rn(src[0]), __float2half_rn(src[1]));
        }
    }
}

// ---------------------------------------------------------------------------
// Merged fp16 mma.sync GEMM, 4-stage pipeline.
// id < 392: GEMM1 -> fp16; else GEMM2 -> fp32.
// ---------------------------------------------------------------------------
__global__ __launch_bounds__(128, 3) void k_gemm_all(
    const __half* __restrict__ A1g, const __half* __restrict__ B1g,
    const __half* __restrict__ A2g, const __half* __restrict__ B2g,
    const float* __restrict__ b_enc, const float* __restrict__ b_dec,
    __half* __restrict__ out1, float* __restrict__ out2)
{
    extern __shared__ __align__(16) char smem[];
    const int id = blockIdx.x;
    const int t = threadIdx.x;
    const int lane = t & 31, wid = t >> 5;
    const int wm = wid >> 1, wn = wid & 1;        // warp tile (wm*64, wn*32)

    const bool g1 = (id < G1_BLOCKS);
    const int j  = g1 ? id : id - G1_BLOCKS;
    const int mt = j >> 3, nt = j & 7;
    const int kSec = g1 ? KSEC1 : KSEC2;
    const __half* Ast = g1 ? A1g : A2g;
    const __half* Bst = g1 ? B1g : B2g;
    const float* bias = g1 ? b_enc : b_dec;

    const char* Abase = (const char*)(Ast + (size_t)mt * kSec * 4096);
    const char* Bbase = (const char*)(Bst + (size_t)nt * kSec * 2048);
    const uint32_t smem_base = smem_u32(smem);

    auto issue = [&](int kc) {
        const int s = kc % STAGES;
        const char* ga = Abase + (size_t)kc * CHUNK_A;
        const char* gb = Bbase + (size_t)kc * CHUNK_B;
        const uint32_t st = smem_base + s * STAGE_BYTES;
        #pragma unroll
        for (int jj = 0; jj < 4; jj++) {   // A: 512 16B-chunks
            int u = t + jj * 128;
            cp16(st + (u >> 2) * SROW + (u & 3) * 16, ga + u * 16);
        }
        #pragma unroll
        for (int jj = 0; jj < 2; jj++) {   // B: 256 16B-chunks
            int u = t + jj * 128;
            cp16(st + SUBT_A + (u >> 2) * SROW + (u & 3) * 16, gb + u * 16);
        }
        asm volatile("cp.async.commit_group;");
    };

    issue(0); issue(1); issue(2);

    float c[4][4][4];
    #pragma unroll
    for (int mi = 0; mi < 4; mi++)
        #pragma unroll
        for (int nj = 0; nj < 4; nj++)
            #pragma unroll
            for (int q = 0; q < 4; q++) c[mi][nj][q] = 0.f;

    for (int kc = 0; kc < kSec; kc++) {
        asm volatile("cp.async.wait_group 2;");
        __syncthreads();
        const int s = kc % STAGES;
        const uint32_t st = smem_base + s * STAGE_BYTES;
        const uint32_t aB = st + (wm * 64 + (lane & 15)) * SROW + (lane >> 4) * 16;
        const uint32_t bB = st + SUBT_A + (wn * 32 + (lane & 15)) * SROW + (lane >> 4) * 16;
        #pragma unroll
        for (int ks = 0; ks < 2; ks++) {
            const uint32_t ko = ks * 32;
            uint32_t a[4][4], bh[2][4];
            #pragma unroll
            for (int mi = 0; mi < 4; mi++) ldm_x4(a[mi], aB + mi * 16 * SROW + ko);
            #pragma unroll
            for (int nj = 0; nj < 2; nj++) ldm_x4(bh[nj], bB + nj * 16 * SROW + ko);
            #pragma unroll
            for (int mi = 0; mi < 4; mi++)
                #pragma unroll
                for (int n8 = 0; n8 < 4; n8++) {
                    const int nj = n8 >> 1, hl = n8 & 1;
                    mma16816(c[mi][n8], a[mi], bh[nj][hl], bh[nj][hl + 2]);
                }
        }
        if (kc + 3 < kSec) issue(kc + 3);
        else asm volatile("cp.async.commit_group;");
    }

    // epilogue
    const int r0b = mt * 128 + wm * 64 + (lane >> 2);
    const int ncb = nt * 64 + wn * 32 + (lane & 3) * 2;
    #pragma unroll
    for (int mi = 0; mi < 4; mi++) {
        #pragma unroll
        for (int n8 = 0; n8 < 4; n8++) {
            const int n = ncb + n8 * 8;
            const float b0 = bias[n], b1 = bias[n + 1];
            const size_t o0 = (size_t)(r0b + mi * 16) * AA + n;
            if (g1) {
                *(__half2*)(out1 + o0) =
                    __floats2half2_rn(c[mi][n8][0] + b0, c[mi][n8][1] + b1);
                *(__half2*)(out1 + o0 + 8 * AA) =
                    __floats2half2_rn(c[mi][n8][2] + b0, c[mi][n8][3] + b1);
            } else {
                float2 v0 = { c[mi][n8][0] + b0, c[mi][n8][1] + b1 };
                float2 v1 = { c[mi][n8][2] + b0, c[mi][n8][3] + b1 };
                *(float2*)(out2 + o0) = v0;
                *(float2*)(out2 + o0 + 8 * AA) = v1;
            }
        }
    }
}

// ---------------------------------------------------------------------------
// K3a: scores. Warp = 2 pixels (d-loads amortized over both); e, w in regs.
// grid (13, B), 256 threads.
// ---------------------------------------------------------------------------
__global__ __launch_bounds__(256) void k_score(
    const float* __restrict__ w_alpha, const float* __restrict__ b_alpha,
    float* __restrict__ score)
{
    __shared__ __half2 sdec[GG * AA / 2];   // 20KB
    __shared__ float sw_[AA];               // 2KB
    const int b = blockIdx.y;
    const int t = threadIdx.x, warp = t >> 5, lane = t & 31;

    const float* dptr = g_att_dec + (size_t)b * GG * AA;
    for (int i = t; i < GG * AA / 2; i += 256) {
        float2 d2 = *(const float2*)&dptr[2 * i];
        sdec[i] = __floats2half2_rn(d2.x, d2.y);
    }
    for (int i = t; i < AA; i += 256) sw_[i] = w_alpha[i];
    __syncthreads();

    const int p0 = blockIdx.x * 16 + warp * 2;
    const int p1 = p0 + 1;
    const bool v0 = (p0 < PP), v1 = (p1 < PP);
    if (!v0) return;
    const int p1c = v1 ? p1 : p0;
    const float ba = b_alpha[0];
    const __half2* ep0 = (const __half2*)(g_att_encH + ((size_t)b * PP + p0) * AA);
    const __half2* ep1 = (const __half2*)(g_att_encH + ((size_t)b * PP + p1c) * AA);

    float2 e0[8], e1[8], w[8];
    #pragma unroll
    for (int i = 0; i < 8; i++) {
        e0[i] = __half22float2(ep0[lane + 32 * i]);
        e1[i] = __half22float2(ep1[lane + 32 * i]);
        w[i]  = *(const float2*)&sw_[2 * (lane + 32 * i)];
    }

    for (int g = 0; g < GG; g++) {
        float s0 = 0.f, s1 = 0.f;
        const __half2* dg = sdec + g * (AA / 2);
        #pragma unroll
        for (int i = 0; i < 8; i++) {
            float2 d2 = __half22float2(dg[lane + 32 * i]);
            s0 = fmaf(fmaxf(e0[i].x + d2.x, 0.f), w[i].x, s0);
            s0 = fmaf(fmaxf(e0[i].y + d2.y, 0.f), w[i].y, s0);
            s1 = fmaf(fmaxf(e1[i].x + d2.x, 0.f), w[i].x, s1);
            s1 = fmaf(fmaxf(e1[i].y + d2.y, 0.f), w[i].y, s1);
        }
        #pragma unroll
        for (int o = 16; o > 0; o >>= 1) {
            s0 += __shfl_xor_sync(0xffffffffu, s0, o);
            s1 += __shfl_xor_sync(0xffffffffu, s1, o);
        }
        if (lane == 0) {
            float* sg = score + ((size_t)b * GG + g) * PP;
            sg[p0] = s0 + ba;
            if (v1) sg[p1] = s1 + ba;
        }
    }
}

// ---------------------------------------------------------------------------
// K3b (fused): 640 threads = 20 warps; warp w owns g = w for softmax AND wsum.
// Alpha reads in wsum are warp-broadcast float4s. grid (8 a-chunks, B).
// ---------------------------------------------------------------------------
__global__ __launch_bounds__(640) void k_soft_wsum(
    const float* __restrict__ score, float* __restrict__ out_alpha,
    float* __restrict__ out_res)
{
    __shared__ __align__(16) float sal[GG * PP];      // 15.7KB
    __shared__ __align__(16) __half2 tile[PP * 32];   // 25KB: [p][32 half2]

    const int b = blockIdx.y, a0 = blockIdx.x * 64;
    const int t = threadIdx.x, warp = t >> 5, lane = t & 31;

    // stage tile via cp.async (1568 16B chunks)
    {
        const char* src = (const char*)(g_att_encH + (size_t)b * PP * AA + a0);
        const uint32_t tb = smem_u32(tile);
        #pragma unroll
        for (int i = 0; i < 3; i++) {
            int u = t + i * 640;
            if (u < PP * 8) {
                int p = u >> 3, c = u & 7;
                cp16(tb + u * 16, src + (size_t)p * AA * 2 + c * 16);
            }
        }
        asm volatile("cp.async.commit_group;");
    }

    // stage scores
    const float* sp = score + (size_t)b * GG * PP;
    for (int i = t; i < GG * PP; i += 640) sal[i] = sp[i];
    __syncthreads();

    // softmax: warp w handles g = w (single round, 20 warps)
    {
        float* row = sal + warp * PP;
        float m = -1e30f;
        for (int p = lane; p < PP; p += 32) m = fmaxf(m, row[p]);
        #pragma unroll
        for (int o = 16; o > 0; o >>= 1)
            m = fmaxf(m, __shfl_xor_sync(0xffffffffu, m, o));
        float sum = 0.f;
        for (int p = lane; p < PP; p += 32) {
            float ex = __expf(row[p] - m);
            row[p] = ex;
            sum += ex;
        }
        #pragma unroll
        for (int o = 16; o > 0; o >>= 1)
            sum += __shfl_xor_sync(0xffffffffu, sum, o);
        const float inv = 1.f / sum;
        for (int p = lane; p < PP; p += 32) row[p] *= inv;
    }
    asm volatile("cp.async.wait_group 0;");
    __syncthreads();

    if (blockIdx.x == 0) {
        float* ao = out_alpha + (size_t)b * GG * PP;
        for (int i = t; i < GG * PP; i += 640) ao[i] = sal[i];
    }

    // wsum: warp = g, lane = half2 column; alpha via broadcast float4 loads
    const int g = warp;
    float2 acc = make_float2(0.f, 0.f);
    const float4* s4 = (const float4*)(sal + g * PP);   // 196 = 49 float4, 16B aligned

    #pragma unroll 7
    for (int p4 = 0; p4 < PP / 4; p4++) {
        float4 A = s4[p4];                              // broadcast (same addr per warp)
        float2 v0 = __half22float2(tile[(4 * p4 + 0) * 32 + lane]);
        float2 v1 = __half22float2(tile[(4 * p4 + 1) * 32 + lane]);
        float2 v2 = __half22float2(tile[(4 * p4 + 2) * 32 + lane]);
        float2 v3 = __half22float2(tile[(4 * p4 + 3) * 32 + lane]);
        acc.x = fmaf(A.x, v0.x, acc.x); acc.y = fmaf(A.x, v0.y, acc.y);
        acc.x = fmaf(A.y, v1.x, acc.x); acc.y = fmaf(A.y, v1.y, acc.y);
        acc.x = fmaf(A.z, v2.x, acc.x); acc.y = fmaf(A.z, v2.y, acc.y);
        acc.x = fmaf(A.w, v3.x, acc.x); acc.y = fmaf(A.w, v3.y, acc.y);
    }
    *(float2*)&out_res[((size_t)b * GG + g) * AA + a0 + 2 * lane] = acc;
}

// ---------------------------------------------------------------------------
extern "C" void kernel_launch(void* const* d_in, const int* in_sizes, int n_in,
                              void* d_out, int out_size)
{
    const float* enc     = (const float*)d_in[0];
    const float* dec     = (const float*)d_in[1];
    const float* W_enc   = (const float*)d_in[2];
    const float* b_enc   = (const float*)d_in[3];
    const float* W_dec   = (const float*)d_in[4];
    const float* b_dec   = (const float*)d_in[5];
    const float* w_alpha = (const float*)d_in[6];
    const float* b_alpha = (const float*)d_in[7];

    float* out = (float*)d_out;
    float* out_res   = out;                        // (B,G,A)
    float* out_alpha = out + (size_t)M2 * AA;      // (B,G,P)

    __half *A1, *B1, *A2, *B2, *attH;
    float *att_dec, *score;
    cudaGetSymbolAddress((void**)&A1, g_A1);
    cudaGetSymbolAddress((void**)&B1, g_B1);
    cudaGetSymbolAddress((void**)&A2, g_A2);
    cudaGetSymbolAddress((void**)&B2, g_B2);
    cudaGetSymbolAddress((void**)&attH, g_att_encH);
    cudaGetSymbolAddress((void**)&att_dec, g_att_dec);
    cudaGetSymbolAddress((void**)&score, g_score);

    cudaFuncSetAttribute(k_gemm_all, cudaFuncAttributeMaxDynamicSharedMemorySize, SMEM_GEMM);

    // 1: all prep (independent blocks)
    k_prep_all<<<3680, 256>>>(enc, dec, W_enc, W_dec, A1, B1, A2, B2);

    // 2: both GEMMs in one wave (432 CTAs @ 3/SM)
    k_gemm_all<<<G1_BLOCKS + G2_BLOCKS, 128, SMEM_GEMM>>>(
        A1, B1, A2, B2, b_enc, b_dec, attH, att_dec);

    // 3: scores (warp = 2p)
    k_score<<<dim3(13, BATCH), 256>>>(w_alpha, b_alpha, score);

    // 4: softmax + weighted sum (warp-per-g)
    k_soft_wsum<<<dim3(8, BATCH), 640>>>(score, out_alpha, out_res);
}